// round 1
// baseline (speedup 1.0000x reference)
#include <cuda_runtime.h>

#define NN   100000
#define NE   1600000
#define INC  26
#define HID  128
#define OUTC 64
#define BN_EPS 1e-5f
#define OUT_ELEMS (NN * OUTC)

// ---------------- device scratch (no allocations allowed) ----------------
__device__ float g_x[NN * HID];      // activations
__device__ float g_agg[NN * HID];    // scatter accumulator (layer0 uses first NN*26)
__device__ float g_norm_src[NN];
__device__ float g_norm_dst[NN];
__device__ float g_deg_out[NN];
__device__ float g_deg_in[NN];
__device__ float g_sum[HID];
__device__ float g_sumsq[HID];
__device__ float g_scale[HID];
__device__ float g_shift[HID];

__constant__ float c_wtable[26] = {
    0.7f,0.9f,0.7f,0.9f,0.3f,0.7f,0.3f,0.9f,0.3f,0.3f,0.9f,0.7f,0.1f,
    0.9f,0.5f,0.9f,0.5f,0.5f,0.1f,0.3f,0.7f,0.9f,0.9f,0.9f,0.9f,0.9f};

// ---------------- utility kernels ----------------
__global__ void k_zero_deg() {
    int n = blockIdx.x * blockDim.x + threadIdx.x;
    if (n < NN) { g_deg_out[n] = 0.f; g_deg_in[n] = 0.f; }
}

__global__ void k_zero_agg(int n4) {
    int i = blockIdx.x * blockDim.x + threadIdx.x;
    if (i < n4) ((float4*)g_agg)[i] = make_float4(0.f, 0.f, 0.f, 0.f);
}

__global__ void k_degrees(const int* __restrict__ src, const int* __restrict__ dst) {
    int e = blockIdx.x * blockDim.x + threadIdx.x;
    if (e < NE) {
        atomicAdd(&g_deg_out[src[e]], 1.f);
        atomicAdd(&g_deg_in[dst[e]], 1.f);
    }
}

// per-node: degree norms + argmax weight written to tail of d_out
__global__ void k_nodeprep(const float* __restrict__ h, float* __restrict__ out) {
    int n = blockIdx.x * blockDim.x + threadIdx.x;
    if (n >= NN) return;
    const float* hr = h + (size_t)n * INC;
    float best = hr[0];
    int bi = 0;
#pragma unroll
    for (int c = 1; c < INC; c++) {
        float v = hr[c];
        if (v > best) { best = v; bi = c; }
    }
    out[OUT_ELEMS + n] = c_wtable[bi];
    g_norm_src[n] = rsqrtf(fmaxf(g_deg_out[n], 1.f));
    g_norm_dst[n] = rsqrtf(fmaxf(g_deg_in[n], 1.f));
}

// ---------------- edge scatter (aggregate-first) ----------------
// layer 0: 26 channels, scalar red
__global__ void k_scatter26(const float* __restrict__ h,
                            const int* __restrict__ src, const int* __restrict__ dst) {
    int gid = blockIdx.x * blockDim.x + threadIdx.x;
    int e = gid >> 5;
    int c = gid & 31;
    if (e >= NE) return;
    int s = src[e];
    if (c < INC) {
        float v = h[(size_t)s * INC + c] * g_norm_src[s];
        float* p = &g_agg[(size_t)dst[e] * INC + c];
        asm volatile("red.global.add.f32 [%0], %1;" :: "l"(p), "f"(v) : "memory");
    }
}

// layers 1/2: 128 channels, one warp per edge, vector red
__global__ void k_scatter128(const int* __restrict__ src, const int* __restrict__ dst) {
    int gid = blockIdx.x * blockDim.x + threadIdx.x;
    int e = gid >> 5;
    int lane = gid & 31;
    if (e >= NE) return;
    int s = src[e];
    int d = dst[e];
    float ns = g_norm_src[s];
    float4 v = ((const float4*)(g_x + (size_t)s * HID))[lane];
    v.x *= ns; v.y *= ns; v.z *= ns; v.w *= ns;
    float* p = g_agg + (size_t)d * HID + lane * 4;
    asm volatile("red.global.add.v4.f32 [%0], {%1,%2,%3,%4};"
                 :: "l"(p), "f"(v.x), "f"(v.y), "f"(v.z), "f"(v.w) : "memory");
}

// ---------------- GEMMs ----------------
// layer 0: [NN,26] @ [26,128], epilogue *norm_dst + bias -> g_x
__global__ void k_gemm_l0(const float* __restrict__ W, const float* __restrict__ b) {
    __shared__ float Wsh[INC * HID];
    __shared__ float xs[8 * INC];
    int c = threadIdx.x; // 0..127
    for (int i = c; i < INC * HID; i += HID) Wsh[i] = W[i];
    float bc = b[c];
    int rbase = blockIdx.x * 64;
    for (int rr = 0; rr < 64; rr += 8) {
        int r = rbase + rr;
        if (r >= NN) break;
        __syncthreads();
        for (int i = c; i < 8 * INC; i += HID) {
            int j = i / INC, k = i - j * INC;
            int gr = r + j;
            xs[i] = (gr < NN) ? g_agg[(size_t)gr * INC + k] : 0.f;
        }
        __syncthreads();
        float acc[8] = {0.f,0.f,0.f,0.f,0.f,0.f,0.f,0.f};
#pragma unroll
        for (int k = 0; k < INC; k++) {
            float w = Wsh[k * HID + c];
#pragma unroll
            for (int j = 0; j < 8; j++) acc[j] = fmaf(xs[j * INC + k], w, acc[j]);
        }
#pragma unroll
        for (int j = 0; j < 8; j++) {
            int gr = r + j;
            if (gr < NN) g_x[(size_t)gr * HID + c] = acc[j] * g_norm_dst[gr] + bc;
        }
    }
}

// layers 1/2: [NN,128] @ [128,128], input g_agg, epilogue *norm_dst + bias -> g_x
#define GEMMH_SMEM ((HID * HID + 8 * HID) * 4)
__global__ void k_gemm_h(const float* __restrict__ W, const float* __restrict__ b) {
    extern __shared__ float smemf[];
    float* Wsh = smemf;              // 16384
    float* xs = smemf + HID * HID;   // 1024
    int c = threadIdx.x;
    for (int i = c; i < HID * HID; i += HID) Wsh[i] = W[i];
    float bc = b[c];
    int rbase = blockIdx.x * 64;
    for (int rr = 0; rr < 64; rr += 8) {
        int r = rbase + rr;
        if (r >= NN) break;
        __syncthreads();
#pragma unroll
        for (int j = 0; j < 8; j++) {
            int gr = r + j;
            xs[j * HID + c] = (gr < NN) ? g_agg[(size_t)gr * HID + c] : 0.f;
        }
        __syncthreads();
        float acc[8] = {0.f,0.f,0.f,0.f,0.f,0.f,0.f,0.f};
        const float4* xv = (const float4*)xs;
#pragma unroll 4
        for (int k4 = 0; k4 < 32; k4++) {
            float w0 = Wsh[(k4 * 4 + 0) * HID + c];
            float w1 = Wsh[(k4 * 4 + 1) * HID + c];
            float w2 = Wsh[(k4 * 4 + 2) * HID + c];
            float w3 = Wsh[(k4 * 4 + 3) * HID + c];
#pragma unroll
            for (int j = 0; j < 8; j++) {
                float4 x4 = xv[j * 32 + k4];
                acc[j] = fmaf(x4.x, w0, acc[j]);
                acc[j] = fmaf(x4.y, w1, acc[j]);
                acc[j] = fmaf(x4.z, w2, acc[j]);
                acc[j] = fmaf(x4.w, w3, acc[j]);
            }
        }
#pragma unroll
        for (int j = 0; j < 8; j++) {
            int gr = r + j;
            if (gr < NN) g_x[(size_t)gr * HID + c] = acc[j] * g_norm_dst[gr] + bc;
        }
    }
}

// final FC: [NN,128] @ [128,64] + bfc -> d_out
__global__ void k_fc(const float* __restrict__ W, const float* __restrict__ b,
                     float* __restrict__ out) {
    __shared__ float Wsh[HID * OUTC];
    __shared__ float xs[8 * HID];
    int c = threadIdx.x; // 0..63
    for (int i = c; i < HID * OUTC; i += OUTC) Wsh[i] = W[i];
    float bc = b[c];
    int rbase = blockIdx.x * 64;
    for (int rr = 0; rr < 64; rr += 8) {
        int r = rbase + rr;
        if (r >= NN) break;
        __syncthreads();
        for (int i = c; i < 8 * HID; i += OUTC) {
            int j = i >> 7, k = i & 127;
            int gr = r + j;
            xs[i] = (gr < NN) ? g_x[(size_t)gr * HID + k] : 0.f;
        }
        __syncthreads();
        float acc[8] = {0.f,0.f,0.f,0.f,0.f,0.f,0.f,0.f};
        const float4* xv = (const float4*)xs;
#pragma unroll 4
        for (int k4 = 0; k4 < 32; k4++) {
            float w0 = Wsh[(k4 * 4 + 0) * OUTC + c];
            float w1 = Wsh[(k4 * 4 + 1) * OUTC + c];
            float w2 = Wsh[(k4 * 4 + 2) * OUTC + c];
            float w3 = Wsh[(k4 * 4 + 3) * OUTC + c];
#pragma unroll
            for (int j = 0; j < 8; j++) {
                float4 x4 = xv[j * 32 + k4];
                acc[j] = fmaf(x4.x, w0, acc[j]);
                acc[j] = fmaf(x4.y, w1, acc[j]);
                acc[j] = fmaf(x4.z, w2, acc[j]);
                acc[j] = fmaf(x4.w, w3, acc[j]);
            }
        }
#pragma unroll
        for (int j = 0; j < 8; j++) {
            int gr = r + j;
            if (gr < NN) out[(size_t)gr * OUTC + c] = acc[j] + bc;
        }
    }
}

// ---------------- batch norm ----------------
__global__ void k_zero_stats() {
    int c = threadIdx.x;
    g_sum[c] = 0.f;
    g_sumsq[c] = 0.f;
}

#define BNROWS 512
__global__ void k_bnstats() {
    int c = threadIdx.x;
    int r0 = blockIdx.x * BNROWS;
    int r1 = min(r0 + BNROWS, NN);
    float s = 0.f, ss = 0.f;
    for (int r = r0; r < r1; r++) {
        float v = g_x[(size_t)r * HID + c];
        s += v;
        ss = fmaf(v, v, ss);
    }
    atomicAdd(&g_sum[c], s);
    atomicAdd(&g_sumsq[c], ss);
}

__global__ void k_bnfinal(const float* __restrict__ g, const float* __restrict__ bt) {
    int c = threadIdx.x;
    float inv_n = 1.f / (float)NN;
    float mu = g_sum[c] * inv_n;
    float var = g_sumsq[c] * inv_n - mu * mu;
    float sc = g[c] * rsqrtf(var + BN_EPS);
    g_scale[c] = sc;
    g_shift[c] = bt[c] - mu * sc;
}

__global__ void k_bnrelu() {
    int i = blockIdx.x * blockDim.x + threadIdx.x; // over NN*32 float4
    if (i >= NN * (HID / 4)) return;
    float4 v = ((float4*)g_x)[i];
    int cb = (i & 31) * 4;
    v.x = fmaxf(fmaf(v.x, g_scale[cb + 0], g_shift[cb + 0]), 0.f);
    v.y = fmaxf(fmaf(v.y, g_scale[cb + 1], g_shift[cb + 1]), 0.f);
    v.z = fmaxf(fmaf(v.z, g_scale[cb + 2], g_shift[cb + 2]), 0.f);
    v.w = fmaxf(fmaf(v.w, g_scale[cb + 3], g_shift[cb + 3]), 0.f);
    ((float4*)g_x)[i] = v;
}

// ---------------- launch ----------------
extern "C" void kernel_launch(void* const* d_in, const int* in_sizes, int n_in,
                              void* d_out, int out_size) {
    const float* h   = (const float*)d_in[0];
    const int*   src = (const int*)d_in[1];
    const int*   dst = (const int*)d_in[2];
    const float* w0  = (const float*)d_in[3];
    const float* b0  = (const float*)d_in[4];
    const float* w1  = (const float*)d_in[5];
    const float* b1  = (const float*)d_in[6];
    const float* w2  = (const float*)d_in[7];
    const float* b2  = (const float*)d_in[8];
    const float* g0  = (const float*)d_in[9];
    const float* bt0 = (const float*)d_in[10];
    const float* g1  = (const float*)d_in[11];
    const float* bt1 = (const float*)d_in[12];
    const float* g2  = (const float*)d_in[13];
    const float* bt2 = (const float*)d_in[14];
    const float* wfc = (const float*)d_in[15];
    const float* bfc = (const float*)d_in[16];
    float* out = (float*)d_out;

    cudaFuncSetAttribute(k_gemm_h, cudaFuncAttributeMaxDynamicSharedMemorySize, GEMMH_SMEM);

    // degrees + norms + node weights
    k_zero_deg<<<(NN + 255) / 256, 256>>>();
    k_degrees<<<(NE + 255) / 256, 256>>>(src, dst);
    k_nodeprep<<<(NN + 255) / 256, 256>>>(h, out);

    // ---- layer 0 (26 -> 128): aggregate-first ----
    k_zero_agg<<<(NN * INC / 4 + 255) / 256, 256>>>(NN * INC / 4);
    k_scatter26<<<(NE * 32 + 255) / 256, 256>>>(h, src, dst);
    k_gemm_l0<<<(NN + 63) / 64, 128>>>(w0, b0);
    k_zero_stats<<<1, 128>>>();
    k_bnstats<<<(NN + BNROWS - 1) / BNROWS, 128>>>();
    k_bnfinal<<<1, 128>>>(g0, bt0);
    k_bnrelu<<<(NN * (HID / 4) + 255) / 256, 256>>>();

    // ---- layers 1, 2 (128 -> 128) ----
    const float* Ws[2]  = {w1, w2};
    const float* bs[2]  = {b1, b2};
    const float* gs[2]  = {g1, g2};
    const float* bts[2] = {bt1, bt2};
    for (int l = 0; l < 2; l++) {
        k_zero_agg<<<(NN * (HID / 4) + 255) / 256, 256>>>(NN * (HID / 4));
        k_scatter128<<<(NE * 32 + 255) / 256, 256>>>(src, dst);
        k_gemm_h<<<(NN + 63) / 64, 128, GEMMH_SMEM>>>(Ws[l], bs[l]);
        k_zero_stats<<<1, 128>>>();
        k_bnstats<<<(NN + BNROWS - 1) / BNROWS, 128>>>();
        k_bnfinal<<<1, 128>>>(gs[l], bts[l]);
        k_bnrelu<<<(NN * (HID / 4) + 255) / 256, 256>>>();
    }

    // ---- final FC (128 -> 64) ----
    k_fc<<<(NN + 63) / 64, 64>>>(wfc, bfc, out);
}

// round 2
// speedup vs baseline: 1.2885x; 1.2885x over previous
#include <cuda_runtime.h>

#define NN   100000
#define NE   1600000
#define INC  26
#define HID  128
#define OUTC 64
#define BN_EPS 1e-5f
#define OUT_ELEMS (NN * OUTC)

// ---------------- device scratch ----------------
__device__ float g_x[NN * HID];      // raw (pre-BN) layer outputs
__device__ float g_agg[NN * HID];    // gather accumulator (layer0 uses NN*26)
__device__ float g_norm_src[NN];
__device__ float g_norm_dst[NN];
__device__ int   g_deg_out_i[NN];
__device__ int   g_deg_in_i[NN];
__device__ int   g_rowptr[NN];
__device__ int   g_cursor[NN];
__device__ int   g_csr_src[NE];
__device__ float g_sum[HID];
__device__ float g_sumsq[HID];
__device__ float g_scale[HID];
__device__ float g_shift[HID];

__constant__ float c_wtable[26] = {
    0.7f,0.9f,0.7f,0.9f,0.3f,0.7f,0.3f,0.9f,0.3f,0.3f,0.9f,0.7f,0.1f,
    0.9f,0.5f,0.9f,0.5f,0.5f,0.1f,0.3f,0.7f,0.9f,0.9f,0.9f,0.9f,0.9f};

// ---------------- prep kernels ----------------
__global__ void k_zero_deg() {
    int n = blockIdx.x * blockDim.x + threadIdx.x;
    if (n < NN) { g_deg_out_i[n] = 0; g_deg_in_i[n] = 0; }
}

__global__ void k_degrees(const int* __restrict__ src, const int* __restrict__ dst) {
    int e = blockIdx.x * blockDim.x + threadIdx.x;
    if (e < NE) {
        atomicAdd(&g_deg_out_i[src[e]], 1);
        atomicAdd(&g_deg_in_i[dst[e]], 1);
    }
}

__global__ void k_nodeprep(const float* __restrict__ h, float* __restrict__ out) {
    int n = blockIdx.x * blockDim.x + threadIdx.x;
    if (n >= NN) return;
    const float* hr = h + (size_t)n * INC;
    float best = hr[0];
    int bi = 0;
#pragma unroll
    for (int c = 1; c < INC; c++) {
        float v = hr[c];
        if (v > best) { best = v; bi = c; }
    }
    out[OUT_ELEMS + n] = c_wtable[bi];
    g_norm_src[n] = rsqrtf(fmaxf((float)g_deg_out_i[n], 1.f));
    g_norm_dst[n] = rsqrtf(fmaxf((float)g_deg_in_i[n], 1.f));
}

// single-block exclusive scan of deg_in -> rowptr (+cursor copy)
__global__ void k_scan() {
    const int T = 1024;
    int tid = threadIdx.x;
    const int chunk = (NN + T - 1) / T;
    int start = tid * chunk;
    int end = min(start + chunk, NN);
    int s = 0;
    for (int i = start; i < end; i++) s += g_deg_in_i[i];
    int lane = tid & 31, wid = tid >> 5;
    int v = s;
#pragma unroll
    for (int o = 1; o < 32; o <<= 1) {
        int t = __shfl_up_sync(0xffffffff, v, o);
        if (lane >= o) v += t;
    }
    __shared__ int wsum[32];
    if (lane == 31) wsum[wid] = v;
    __syncthreads();
    if (wid == 0) {
        int w = wsum[lane];
#pragma unroll
        for (int o = 1; o < 32; o <<= 1) {
            int t = __shfl_up_sync(0xffffffff, w, o);
            if (lane >= o) w += t;
        }
        wsum[lane] = w;
    }
    __syncthreads();
    int excl = v - s + (wid > 0 ? wsum[wid - 1] : 0);
    int run = excl;
    for (int i = start; i < end; i++) {
        g_rowptr[i] = run;
        g_cursor[i] = run;
        run += g_deg_in_i[i];
    }
}

__global__ void k_fill(const int* __restrict__ src, const int* __restrict__ dst) {
    int e = blockIdx.x * blockDim.x + threadIdx.x;
    if (e < NE) {
        int pos = atomicAdd(&g_cursor[dst[e]], 1);
        g_csr_src[pos] = src[e];
    }
}

// ---------------- gather-aggregate (CSR, warp per node) ----------------
__global__ void k_gather26(const float* __restrict__ h) {
    int gid = blockIdx.x * blockDim.x + threadIdx.x;
    int n = gid >> 5;
    int c = gid & 31;
    if (n >= NN) return;
    int start = g_rowptr[n];
    int cnt = g_deg_in_i[n];
    float acc = 0.f;
    if (c < INC) {
        int i = 0;
        for (; i + 2 <= cnt; i += 2) {
            int s0 = g_csr_src[start + i];
            int s1 = g_csr_src[start + i + 1];
            float v0 = h[(size_t)s0 * INC + c];
            float v1 = h[(size_t)s1 * INC + c];
            acc = fmaf(v0, g_norm_src[s0], acc);
            acc = fmaf(v1, g_norm_src[s1], acc);
        }
        if (i < cnt) {
            int s0 = g_csr_src[start + i];
            acc = fmaf(h[(size_t)s0 * INC + c], g_norm_src[s0], acc);
        }
        g_agg[(size_t)n * INC + c] = acc;
    }
}

// reads raw g_x, applies prev-layer BN scale/shift + ReLU + norm_src on the fly
__global__ void k_gather128() {
    int gid = blockIdx.x * blockDim.x + threadIdx.x;
    int n = gid >> 5;
    int lane = gid & 31;
    if (n >= NN) return;
    int start = g_rowptr[n];
    int cnt = g_deg_in_i[n];
    float4 sc = ((const float4*)g_scale)[lane];
    float4 sh = ((const float4*)g_shift)[lane];
    float4 acc = make_float4(0.f, 0.f, 0.f, 0.f);
    int i = 0;
    for (; i + 2 <= cnt; i += 2) {
        int s0 = g_csr_src[start + i];
        int s1 = g_csr_src[start + i + 1];
        float ns0 = g_norm_src[s0];
        float ns1 = g_norm_src[s1];
        float4 v0 = ((const float4*)(g_x + (size_t)s0 * HID))[lane];
        float4 v1 = ((const float4*)(g_x + (size_t)s1 * HID))[lane];
        acc.x = fmaf(fmaxf(fmaf(v0.x, sc.x, sh.x), 0.f), ns0, acc.x);
        acc.y = fmaf(fmaxf(fmaf(v0.y, sc.y, sh.y), 0.f), ns0, acc.y);
        acc.z = fmaf(fmaxf(fmaf(v0.z, sc.z, sh.z), 0.f), ns0, acc.z);
        acc.w = fmaf(fmaxf(fmaf(v0.w, sc.w, sh.w), 0.f), ns0, acc.w);
        acc.x = fmaf(fmaxf(fmaf(v1.x, sc.x, sh.x), 0.f), ns1, acc.x);
        acc.y = fmaf(fmaxf(fmaf(v1.y, sc.y, sh.y), 0.f), ns1, acc.y);
        acc.z = fmaf(fmaxf(fmaf(v1.z, sc.z, sh.z), 0.f), ns1, acc.z);
        acc.w = fmaf(fmaxf(fmaf(v1.w, sc.w, sh.w), 0.f), ns1, acc.w);
    }
    if (i < cnt) {
        int s0 = g_csr_src[start + i];
        float ns0 = g_norm_src[s0];
        float4 v0 = ((const float4*)(g_x + (size_t)s0 * HID))[lane];
        acc.x = fmaf(fmaxf(fmaf(v0.x, sc.x, sh.x), 0.f), ns0, acc.x);
        acc.y = fmaf(fmaxf(fmaf(v0.y, sc.y, sh.y), 0.f), ns0, acc.y);
        acc.z = fmaf(fmaxf(fmaf(v0.z, sc.z, sh.z), 0.f), ns0, acc.z);
        acc.w = fmaf(fmaxf(fmaf(v0.w, sc.w, sh.w), 0.f), ns0, acc.w);
    }
    ((float4*)(g_agg + (size_t)n * HID))[lane] = acc;
}

// ---------------- GEMMs (with BN stats epilogue) ----------------
__global__ void k_zero_stats() {
    int c = threadIdx.x;
    g_sum[c] = 0.f;
    g_sumsq[c] = 0.f;
}

__global__ void k_gemm_l0(const float* __restrict__ W, const float* __restrict__ b) {
    __shared__ float Wsh[INC * HID];
    __shared__ float xs[8 * INC];
    int c = threadIdx.x; // 0..127
    for (int i = c; i < INC * HID; i += HID) Wsh[i] = W[i];
    float bc = b[c];
    float s = 0.f, ss = 0.f;
    int rbase = blockIdx.x * 64;
    for (int rr = 0; rr < 64; rr += 8) {
        int r = rbase + rr;
        if (r >= NN) break;
        __syncthreads();
        for (int i = c; i < 8 * INC; i += HID) {
            int j = i / INC, k = i - j * INC;
            int gr = r + j;
            xs[i] = (gr < NN) ? g_agg[(size_t)gr * INC + k] : 0.f;
        }
        __syncthreads();
        float acc[8] = {0.f,0.f,0.f,0.f,0.f,0.f,0.f,0.f};
#pragma unroll
        for (int k = 0; k < INC; k++) {
            float w = Wsh[k * HID + c];
#pragma unroll
            for (int j = 0; j < 8; j++) acc[j] = fmaf(xs[j * INC + k], w, acc[j]);
        }
#pragma unroll
        for (int j = 0; j < 8; j++) {
            int gr = r + j;
            if (gr < NN) {
                float y = acc[j] * g_norm_dst[gr] + bc;
                g_x[(size_t)gr * HID + c] = y;
                s += y;
                ss = fmaf(y, y, ss);
            }
        }
    }
    atomicAdd(&g_sum[c], s);
    atomicAdd(&g_sumsq[c], ss);
}

#define GEMMH_SMEM ((HID * HID + 8 * HID) * 4)
__global__ void k_gemm_h(const float* __restrict__ W, const float* __restrict__ b) {
    extern __shared__ float smemf[];
    float* Wsh = smemf;
    float* xs = smemf + HID * HID;
    int c = threadIdx.x;
    for (int i = c; i < HID * HID; i += HID) Wsh[i] = W[i];
    float bc = b[c];
    float s = 0.f, ss = 0.f;
    int rbase = blockIdx.x * 64;
    for (int rr = 0; rr < 64; rr += 8) {
        int r = rbase + rr;
        if (r >= NN) break;
        __syncthreads();
#pragma unroll
        for (int j = 0; j < 8; j++) {
            int gr = r + j;
            xs[j * HID + c] = (gr < NN) ? g_agg[(size_t)gr * HID + c] : 0.f;
        }
        __syncthreads();
        float acc[8] = {0.f,0.f,0.f,0.f,0.f,0.f,0.f,0.f};
        const float4* xv = (const float4*)xs;
#pragma unroll 4
        for (int k4 = 0; k4 < 32; k4++) {
            float w0 = Wsh[(k4 * 4 + 0) * HID + c];
            float w1 = Wsh[(k4 * 4 + 1) * HID + c];
            float w2 = Wsh[(k4 * 4 + 2) * HID + c];
            float w3 = Wsh[(k4 * 4 + 3) * HID + c];
#pragma unroll
            for (int j = 0; j < 8; j++) {
                float4 x4 = xv[j * 32 + k4];
                acc[j] = fmaf(x4.x, w0, acc[j]);
                acc[j] = fmaf(x4.y, w1, acc[j]);
                acc[j] = fmaf(x4.z, w2, acc[j]);
                acc[j] = fmaf(x4.w, w3, acc[j]);
            }
        }
#pragma unroll
        for (int j = 0; j < 8; j++) {
            int gr = r + j;
            if (gr < NN) {
                float y = acc[j] * g_norm_dst[gr] + bc;
                g_x[(size_t)gr * HID + c] = y;
                s += y;
                ss = fmaf(y, y, ss);
            }
        }
    }
    atomicAdd(&g_sum[c], s);
    atomicAdd(&g_sumsq[c], ss);
}

__global__ void k_bnfinal(const float* __restrict__ g, const float* __restrict__ bt) {
    int c = threadIdx.x;
    float inv_n = 1.f / (float)NN;
    float mu = g_sum[c] * inv_n;
    float var = g_sumsq[c] * inv_n - mu * mu;
    float sc = g[c] * rsqrtf(var + BN_EPS);
    g_scale[c] = sc;
    g_shift[c] = bt[c] - mu * sc;
}

// final FC: applies BN2 + ReLU on load, then [NN,128]@[128,64]+bfc -> d_out
__global__ void k_fc(const float* __restrict__ W, const float* __restrict__ b,
                     float* __restrict__ out) {
    __shared__ float Wsh[HID * OUTC];
    __shared__ float xs[8 * HID];
    __shared__ float scs[HID], shs[HID];
    int c = threadIdx.x; // 0..63
    for (int i = c; i < HID * OUTC; i += OUTC) Wsh[i] = W[i];
    for (int i = c; i < HID; i += OUTC) { scs[i] = g_scale[i]; shs[i] = g_shift[i]; }
    float bc = b[c];
    int rbase = blockIdx.x * 64;
    for (int rr = 0; rr < 64; rr += 8) {
        int r = rbase + rr;
        if (r >= NN) break;
        __syncthreads();
        for (int i = c; i < 8 * HID; i += OUTC) {
            int j = i >> 7, k = i & 127;
            int gr = r + j;
            float v = (gr < NN) ? g_x[(size_t)gr * HID + k] : 0.f;
            xs[i] = fmaxf(fmaf(v, scs[k], shs[k]), 0.f);
        }
        __syncthreads();
        float acc[8] = {0.f,0.f,0.f,0.f,0.f,0.f,0.f,0.f};
        const float4* xv = (const float4*)xs;
#pragma unroll 4
        for (int k4 = 0; k4 < 32; k4++) {
            float w0 = Wsh[(k4 * 4 + 0) * OUTC + c];
            float w1 = Wsh[(k4 * 4 + 1) * OUTC + c];
            float w2 = Wsh[(k4 * 4 + 2) * OUTC + c];
            float w3 = Wsh[(k4 * 4 + 3) * OUTC + c];
#pragma unroll
            for (int j = 0; j < 8; j++) {
                float4 x4 = xv[j * 32 + k4];
                acc[j] = fmaf(x4.x, w0, acc[j]);
                acc[j] = fmaf(x4.y, w1, acc[j]);
                acc[j] = fmaf(x4.z, w2, acc[j]);
                acc[j] = fmaf(x4.w, w3, acc[j]);
            }
        }
#pragma unroll
        for (int j = 0; j < 8; j++) {
            int gr = r + j;
            if (gr < NN) out[(size_t)gr * OUTC + c] = acc[j] + bc;
        }
    }
}

// ---------------- launch ----------------
extern "C" void kernel_launch(void* const* d_in, const int* in_sizes, int n_in,
                              void* d_out, int out_size) {
    const float* h   = (const float*)d_in[0];
    const int*   src = (const int*)d_in[1];
    const int*   dst = (const int*)d_in[2];
    const float* w0  = (const float*)d_in[3];
    const float* b0  = (const float*)d_in[4];
    const float* w1  = (const float*)d_in[5];
    const float* b1  = (const float*)d_in[6];
    const float* w2  = (const float*)d_in[7];
    const float* b2  = (const float*)d_in[8];
    const float* g0  = (const float*)d_in[9];
    const float* bt0 = (const float*)d_in[10];
    const float* g1  = (const float*)d_in[11];
    const float* bt1 = (const float*)d_in[12];
    const float* g2  = (const float*)d_in[13];
    const float* bt2 = (const float*)d_in[14];
    const float* wfc = (const float*)d_in[15];
    const float* bfc = (const float*)d_in[16];
    float* out = (float*)d_out;

    cudaFuncSetAttribute(k_gemm_h, cudaFuncAttributeMaxDynamicSharedMemorySize, GEMMH_SMEM);

    // graph prep: degrees, norms, node weights, CSR
    k_zero_deg<<<(NN + 255) / 256, 256>>>();
    k_degrees<<<(NE + 255) / 256, 256>>>(src, dst);
    k_nodeprep<<<(NN + 255) / 256, 256>>>(h, out);
    k_scan<<<1, 1024>>>();
    k_fill<<<(NE + 255) / 256, 256>>>(src, dst);

    // ---- layer 0 (26 -> 128) ----
    k_gather26<<<(NN * 32 + 255) / 256, 256>>>(h);
    k_zero_stats<<<1, HID>>>();
    k_gemm_l0<<<(NN + 63) / 64, 128>>>(w0, b0);
    k_bnfinal<<<1, HID>>>(g0, bt0);

    // ---- layers 1, 2 (128 -> 128) ----
    const float* Ws[2]  = {w1, w2};
    const float* bs[2]  = {b1, b2};
    const float* gs[2]  = {g1, g2};
    const float* bts[2] = {bt1, bt2};
    for (int l = 0; l < 2; l++) {
        k_gather128<<<(NN * 32 + 255) / 256, 256>>>();
        k_zero_stats<<<1, HID>>>();
        k_gemm_h<<<(NN + 63) / 64, 128, GEMMH_SMEM>>>(Ws[l], bs[l]);
        k_bnfinal<<<1, HID>>>(gs[l], bts[l]);
    }

    // ---- final FC (128 -> 64), BN2+ReLU fused into load ----
    k_fc<<<(NN + 63) / 64, 64>>>(wfc, bfc, out);
}

// round 3
// speedup vs baseline: 1.5853x; 1.2303x over previous
#include <cuda_runtime.h>

#define NN   100000
#define NE   1600000
#define INC  26
#define HID  128
#define OUTC 64
#define BN_EPS 1e-5f
#define OUT_ELEMS (NN * OUTC)

// ---------------- device scratch ----------------
__device__ float g_x[NN * HID];      // layer activations (raw, then pre-scaled in place)
__device__ float g_agg[NN * HID];    // gather accumulator (layer0 uses NN*26)
__device__ float g_norm_src[NN];
__device__ float g_norm_dst[NN];
__device__ int   g_deg_out_i[NN];
__device__ int   g_deg_in_i[NN];
__device__ int   g_rowptr[NN];
__device__ int   g_cursor[NN];
__device__ int   g_csr_src[NE];
__device__ int   g_total;
__device__ float g_sum[HID];
__device__ float g_sumsq[HID];
__device__ float g_scale[HID];
__device__ float g_shift[HID];

__constant__ float c_wtable[26] = {
    0.7f,0.9f,0.7f,0.9f,0.3f,0.7f,0.3f,0.9f,0.3f,0.3f,0.9f,0.7f,0.1f,
    0.9f,0.5f,0.9f,0.5f,0.5f,0.1f,0.3f,0.7f,0.9f,0.9f,0.9f,0.9f,0.9f};

// ---------------- prep kernels ----------------
__global__ void k_zero_deg() {
    int n = blockIdx.x * blockDim.x + threadIdx.x;
    if (n < NN) { g_deg_out_i[n] = 0; g_deg_in_i[n] = 0; }
    if (n == 0) g_total = 0;
}

__global__ void k_degrees(const int* __restrict__ src, const int* __restrict__ dst) {
    int e = blockIdx.x * blockDim.x + threadIdx.x;
    if (e < NE) {
        atomicAdd(&g_deg_out_i[src[e]], 1);
        atomicAdd(&g_deg_in_i[dst[e]], 1);
    }
}

__global__ void k_nodeprep(const float* __restrict__ h, float* __restrict__ out) {
    int n = blockIdx.x * blockDim.x + threadIdx.x;
    if (n >= NN) return;
    const float* hr = h + (size_t)n * INC;
    float best = hr[0];
    int bi = 0;
#pragma unroll
    for (int c = 1; c < INC; c++) {
        float v = hr[c];
        if (v > best) { best = v; bi = c; }
    }
    out[OUT_ELEMS + n] = c_wtable[bi];
    g_norm_src[n] = rsqrtf(fmaxf((float)g_deg_out_i[n], 1.f));
    g_norm_dst[n] = rsqrtf(fmaxf((float)g_deg_in_i[n], 1.f));
}

// warp-aggregated segment allocator: rowptr[n] = disjoint contiguous range of
// size deg_in[n] (node order irrelevant for the gather)
__global__ void k_alloc() {
    int n = blockIdx.x * blockDim.x + threadIdx.x;
    int lane = threadIdx.x & 31;
    int d = (n < NN) ? g_deg_in_i[n] : 0;
    int incl = d;
#pragma unroll
    for (int o = 1; o < 32; o <<= 1) {
        int t = __shfl_up_sync(0xffffffff, incl, o);
        if (lane >= o) incl += t;
    }
    int wtotal = __shfl_sync(0xffffffff, incl, 31);
    int base = 0;
    if (lane == 0) base = atomicAdd(&g_total, wtotal);
    base = __shfl_sync(0xffffffff, base, 0);
    if (n < NN) {
        int pos = base + incl - d;
        g_rowptr[n] = pos;
        g_cursor[n] = pos;
    }
}

__global__ void k_fill(const int* __restrict__ src, const int* __restrict__ dst) {
    int e = blockIdx.x * blockDim.x + threadIdx.x;
    if (e < NE) {
        int pos = atomicAdd(&g_cursor[dst[e]], 1);
        g_csr_src[pos] = src[e];
    }
}

// ---------------- gather-aggregate (CSR, warp per node) ----------------
__global__ void k_gather26(const float* __restrict__ h) {
    int gid = blockIdx.x * blockDim.x + threadIdx.x;
    int n = gid >> 5;
    int c = gid & 31;
    if (n >= NN) return;
    int start = g_rowptr[n];
    int cnt = g_deg_in_i[n];
    if (c < INC) {
        float acc = 0.f;
        int i = 0;
        for (; i + 2 <= cnt; i += 2) {
            int s0 = g_csr_src[start + i];
            int s1 = g_csr_src[start + i + 1];
            acc = fmaf(h[(size_t)s0 * INC + c], g_norm_src[s0], acc);
            acc = fmaf(h[(size_t)s1 * INC + c], g_norm_src[s1], acc);
        }
        if (i < cnt) {
            int s0 = g_csr_src[start + i];
            acc = fmaf(h[(size_t)s0 * INC + c], g_norm_src[s0], acc);
        }
        g_agg[(size_t)n * INC + c] = acc;
    }
}

// pre-scale: g_x <- relu(bn(g_x)) * norm_src[row], in place
__global__ void k_prescale() {
    int i = blockIdx.x * blockDim.x + threadIdx.x; // over NN*32 float4
    if (i >= NN * (HID / 4)) return;
    int lane = i & 31;
    int row = i >> 5;
    float4 sc = ((const float4*)g_scale)[lane];
    float4 sh = ((const float4*)g_shift)[lane];
    float ns = g_norm_src[row];
    float4 v = ((float4*)g_x)[i];
    v.x = fmaxf(fmaf(v.x, sc.x, sh.x), 0.f) * ns;
    v.y = fmaxf(fmaf(v.y, sc.y, sh.y), 0.f) * ns;
    v.z = fmaxf(fmaf(v.z, sc.z, sh.z), 0.f) * ns;
    v.w = fmaxf(fmaf(v.w, sc.w, sh.w), 0.f) * ns;
    ((float4*)g_x)[i] = v;
}

// pure-sum gather over pre-scaled activations
__global__ void k_gather128() {
    int gid = blockIdx.x * blockDim.x + threadIdx.x;
    int n = gid >> 5;
    int lane = gid & 31;
    if (n >= NN) return;
    int start = g_rowptr[n];
    int cnt = g_deg_in_i[n];
    float4 acc = make_float4(0.f, 0.f, 0.f, 0.f);
    int i = 0;
    for (; i + 4 <= cnt; i += 4) {
        int s0 = g_csr_src[start + i];
        int s1 = g_csr_src[start + i + 1];
        int s2 = g_csr_src[start + i + 2];
        int s3 = g_csr_src[start + i + 3];
        float4 v0 = __ldg((const float4*)(g_x + (size_t)s0 * HID) + lane);
        float4 v1 = __ldg((const float4*)(g_x + (size_t)s1 * HID) + lane);
        float4 v2 = __ldg((const float4*)(g_x + (size_t)s2 * HID) + lane);
        float4 v3 = __ldg((const float4*)(g_x + (size_t)s3 * HID) + lane);
        acc.x += (v0.x + v1.x) + (v2.x + v3.x);
        acc.y += (v0.y + v1.y) + (v2.y + v3.y);
        acc.z += (v0.z + v1.z) + (v2.z + v3.z);
        acc.w += (v0.w + v1.w) + (v2.w + v3.w);
    }
    for (; i < cnt; i++) {
        int s0 = g_csr_src[start + i];
        float4 v0 = __ldg((const float4*)(g_x + (size_t)s0 * HID) + lane);
        acc.x += v0.x; acc.y += v0.y; acc.z += v0.z; acc.w += v0.w;
    }
    ((float4*)(g_agg + (size_t)n * HID))[lane] = acc;
}

// ---------------- GEMMs (with BN stats epilogue) ----------------
__global__ void k_zero_stats() {
    int c = threadIdx.x;
    g_sum[c] = 0.f;
    g_sumsq[c] = 0.f;
}

__global__ void k_gemm_l0(const float* __restrict__ W, const float* __restrict__ b) {
    __shared__ float Wsh[INC * HID];
    __shared__ float xs[8 * INC];
    int c = threadIdx.x; // 0..127
    for (int i = c; i < INC * HID; i += HID) Wsh[i] = W[i];
    float bc = b[c];
    float s = 0.f, ss = 0.f;
    int rbase = blockIdx.x * 64;
    for (int rr = 0; rr < 64; rr += 8) {
        int r = rbase + rr;
        if (r >= NN) break;
        __syncthreads();
        for (int i = c; i < 8 * INC; i += HID) {
            int j = i / INC, k = i - j * INC;
            int gr = r + j;
            xs[i] = (gr < NN) ? g_agg[(size_t)gr * INC + k] : 0.f;
        }
        __syncthreads();
        float acc[8] = {0.f,0.f,0.f,0.f,0.f,0.f,0.f,0.f};
#pragma unroll
        for (int k = 0; k < INC; k++) {
            float w = Wsh[k * HID + c];
#pragma unroll
            for (int j = 0; j < 8; j++) acc[j] = fmaf(xs[j * INC + k], w, acc[j]);
        }
#pragma unroll
        for (int j = 0; j < 8; j++) {
            int gr = r + j;
            if (gr < NN) {
                float y = acc[j] * g_norm_dst[gr] + bc;
                g_x[(size_t)gr * HID + c] = y;
                s += y;
                ss = fmaf(y, y, ss);
            }
        }
    }
    atomicAdd(&g_sum[c], s);
    atomicAdd(&g_sumsq[c], ss);
}

#define GEMMH_SMEM ((HID * HID + 8 * HID) * 4)
__global__ void k_gemm_h(const float* __restrict__ W, const float* __restrict__ b) {
    extern __shared__ float smemf[];
    float* Wsh = smemf;
    float* xs = smemf + HID * HID;
    int c = threadIdx.x;
    for (int i = c; i < HID * HID; i += HID) Wsh[i] = W[i];
    float bc = b[c];
    float s = 0.f, ss = 0.f;
    int rbase = blockIdx.x * 64;
    for (int rr = 0; rr < 64; rr += 8) {
        int r = rbase + rr;
        if (r >= NN) break;
        __syncthreads();
#pragma unroll
        for (int j = 0; j < 8; j++) {
            int gr = r + j;
            xs[j * HID + c] = (gr < NN) ? g_agg[(size_t)gr * HID + c] : 0.f;
        }
        __syncthreads();
        float acc[8] = {0.f,0.f,0.f,0.f,0.f,0.f,0.f,0.f};
        const float4* xv = (const float4*)xs;
#pragma unroll 4
        for (int k4 = 0; k4 < 32; k4++) {
            float w0 = Wsh[(k4 * 4 + 0) * HID + c];
            float w1 = Wsh[(k4 * 4 + 1) * HID + c];
            float w2 = Wsh[(k4 * 4 + 2) * HID + c];
            float w3 = Wsh[(k4 * 4 + 3) * HID + c];
#pragma unroll
            for (int j = 0; j < 8; j++) {
                float4 x4 = xv[j * 32 + k4];
                acc[j] = fmaf(x4.x, w0, acc[j]);
                acc[j] = fmaf(x4.y, w1, acc[j]);
                acc[j] = fmaf(x4.z, w2, acc[j]);
                acc[j] = fmaf(x4.w, w3, acc[j]);
            }
        }
#pragma unroll
        for (int j = 0; j < 8; j++) {
            int gr = r + j;
            if (gr < NN) {
                float y = acc[j] * g_norm_dst[gr] + bc;
                g_x[(size_t)gr * HID + c] = y;
                s += y;
                ss = fmaf(y, y, ss);
            }
        }
    }
    atomicAdd(&g_sum[c], s);
    atomicAdd(&g_sumsq[c], ss);
}

__global__ void k_bnfinal(const float* __restrict__ g, const float* __restrict__ bt) {
    int c = threadIdx.x;
    float inv_n = 1.f / (float)NN;
    float mu = g_sum[c] * inv_n;
    float var = g_sumsq[c] * inv_n - mu * mu;
    float sc = g[c] * rsqrtf(var + BN_EPS);
    g_scale[c] = sc;
    g_shift[c] = bt[c] - mu * sc;
}

// final FC: applies BN2 + ReLU on load, then [NN,128]@[128,64]+bfc -> d_out
__global__ void k_fc(const float* __restrict__ W, const float* __restrict__ b,
                     float* __restrict__ out) {
    __shared__ float Wsh[HID * OUTC];
    __shared__ float xs[8 * HID];
    __shared__ float scs[HID], shs[HID];
    int c = threadIdx.x; // 0..63
    for (int i = c; i < HID * OUTC; i += OUTC) Wsh[i] = W[i];
    for (int i = c; i < HID; i += OUTC) { scs[i] = g_scale[i]; shs[i] = g_shift[i]; }
    float bc = b[c];
    int rbase = blockIdx.x * 64;
    for (int rr = 0; rr < 64; rr += 8) {
        int r = rbase + rr;
        if (r >= NN) break;
        __syncthreads();
        for (int i = c; i < 8 * HID; i += OUTC) {
            int j = i >> 7, k = i & 127;
            int gr = r + j;
            float v = (gr < NN) ? g_x[(size_t)gr * HID + k] : 0.f;
            xs[i] = fmaxf(fmaf(v, scs[k], shs[k]), 0.f);
        }
        __syncthreads();
        float acc[8] = {0.f,0.f,0.f,0.f,0.f,0.f,0.f,0.f};
        const float4* xv = (const float4*)xs;
#pragma unroll 4
        for (int k4 = 0; k4 < 32; k4++) {
            float w0 = Wsh[(k4 * 4 + 0) * OUTC + c];
            float w1 = Wsh[(k4 * 4 + 1) * OUTC + c];
            float w2 = Wsh[(k4 * 4 + 2) * OUTC + c];
            float w3 = Wsh[(k4 * 4 + 3) * OUTC + c];
#pragma unroll
            for (int j = 0; j < 8; j++) {
                float4 x4 = xv[j * 32 + k4];
                acc[j] = fmaf(x4.x, w0, acc[j]);
                acc[j] = fmaf(x4.y, w1, acc[j]);
                acc[j] = fmaf(x4.z, w2, acc[j]);
                acc[j] = fmaf(x4.w, w3, acc[j]);
            }
        }
#pragma unroll
        for (int j = 0; j < 8; j++) {
            int gr = r + j;
            if (gr < NN) out[(size_t)gr * OUTC + c] = acc[j] + bc;
        }
    }
}

// ---------------- launch ----------------
extern "C" void kernel_launch(void* const* d_in, const int* in_sizes, int n_in,
                              void* d_out, int out_size) {
    const float* h   = (const float*)d_in[0];
    const int*   src = (const int*)d_in[1];
    const int*   dst = (const int*)d_in[2];
    const float* w0  = (const float*)d_in[3];
    const float* b0  = (const float*)d_in[4];
    const float* w1  = (const float*)d_in[5];
    const float* b1  = (const float*)d_in[6];
    const float* w2  = (const float*)d_in[7];
    const float* b2  = (const float*)d_in[8];
    const float* g0  = (const float*)d_in[9];
    const float* bt0 = (const float*)d_in[10];
    const float* g1  = (const float*)d_in[11];
    const float* bt1 = (const float*)d_in[12];
    const float* g2  = (const float*)d_in[13];
    const float* bt2 = (const float*)d_in[14];
    const float* wfc = (const float*)d_in[15];
    const float* bfc = (const float*)d_in[16];
    float* out = (float*)d_out;

    cudaFuncSetAttribute(k_gemm_h, cudaFuncAttributeMaxDynamicSharedMemorySize, GEMMH_SMEM);

    // graph prep: degrees, norms, node weights, CSR (parallel alloc, no scan)
    k_zero_deg<<<(NN + 255) / 256, 256>>>();
    k_degrees<<<(NE + 255) / 256, 256>>>(src, dst);
    k_nodeprep<<<(NN + 255) / 256, 256>>>(h, out);
    k_alloc<<<(NN + 255) / 256, 256>>>();
    k_fill<<<(NE + 255) / 256, 256>>>(src, dst);

    // ---- layer 0 (26 -> 128) ----
    k_gather26<<<(NN * 32 + 255) / 256, 256>>>(h);
    k_zero_stats<<<1, HID>>>();
    k_gemm_l0<<<(NN + 63) / 64, 128>>>(w0, b0);
    k_bnfinal<<<1, HID>>>(g0, bt0);

    // ---- layers 1, 2 (128 -> 128) ----
    const float* Ws[2]  = {w1, w2};
    const float* bs[2]  = {b1, b2};
    const float* gs[2]  = {g1, g2};
    const float* bts[2] = {bt1, bt2};
    for (int l = 0; l < 2; l++) {
        k_prescale<<<(NN * (HID / 4) + 255) / 256, 256>>>();
        k_gather128<<<(NN * 32 + 255) / 256, 256>>>();
        k_zero_stats<<<1, HID>>>();
        k_gemm_h<<<(NN + 63) / 64, 128, GEMMH_SMEM>>>(Ws[l], bs[l]);
        k_bnfinal<<<1, HID>>>(gs[l], bts[l]);
    }

    // ---- final FC (128 -> 64), BN2+ReLU fused into load ----
    k_fc<<<(NN + 63) / 64, 64>>>(wfc, bfc, out);
}

// round 4
// speedup vs baseline: 1.6864x; 1.0637x over previous
#include <cuda_runtime.h>
#include <cuda_fp16.h>

#define NN   100000
#define NE   1600000
#define INC  26
#define HID  128
#define OUTC 64
#define BN_EPS 1e-5f
#define OUT_ELEMS (NN * OUTC)

// ---------------- device scratch ----------------
__device__ float  g_x[NN * HID];    // raw (pre-BN) layer outputs, fp32
__device__ __half g_xh[NN * HID];   // pre-scaled activations, fp16 (gather input)
__device__ float  g_agg[NN * HID];  // gather accumulator (layer0 uses NN*26)
__device__ float  g_norm_src[NN];
__device__ float  g_norm_dst[NN];
__device__ int    g_deg_out_i[NN];
__device__ int    g_deg_in_i[NN];
__device__ int    g_rowptr[NN];
__device__ int    g_cursor[NN];
__device__ int    g_csr_src[NE];
__device__ int    g_total;
__device__ float  g_sum[HID];
__device__ float  g_sumsq[HID];
__device__ float  g_scale[HID];
__device__ float  g_shift[HID];

__constant__ float c_wtable[26] = {
    0.7f,0.9f,0.7f,0.9f,0.3f,0.7f,0.3f,0.9f,0.3f,0.3f,0.9f,0.7f,0.1f,
    0.9f,0.5f,0.9f,0.5f,0.5f,0.1f,0.3f,0.7f,0.9f,0.9f,0.9f,0.9f,0.9f};

// ---------------- prep kernels ----------------
__global__ void k_zero_deg() {
    int n = blockIdx.x * blockDim.x + threadIdx.x;
    if (n < NN) { g_deg_out_i[n] = 0; g_deg_in_i[n] = 0; }
    if (n == 0) g_total = 0;
}

__global__ void k_degrees(const int* __restrict__ src, const int* __restrict__ dst) {
    int e = blockIdx.x * blockDim.x + threadIdx.x;
    if (e < NE) {
        atomicAdd(&g_deg_out_i[src[e]], 1);
        atomicAdd(&g_deg_in_i[dst[e]], 1);
    }
}

__global__ void k_nodeprep(const float* __restrict__ h, float* __restrict__ out) {
    int n = blockIdx.x * blockDim.x + threadIdx.x;
    if (n >= NN) return;
    const float* hr = h + (size_t)n * INC;
    float best = hr[0];
    int bi = 0;
#pragma unroll
    for (int c = 1; c < INC; c++) {
        float v = hr[c];
        if (v > best) { best = v; bi = c; }
    }
    out[OUT_ELEMS + n] = c_wtable[bi];
    g_norm_src[n] = rsqrtf(fmaxf((float)g_deg_out_i[n], 1.f));
    g_norm_dst[n] = rsqrtf(fmaxf((float)g_deg_in_i[n], 1.f));
}

// warp-aggregated segment allocator (node order irrelevant for the gather)
__global__ void k_alloc() {
    int n = blockIdx.x * blockDim.x + threadIdx.x;
    int lane = threadIdx.x & 31;
    int d = (n < NN) ? g_deg_in_i[n] : 0;
    int incl = d;
#pragma unroll
    for (int o = 1; o < 32; o <<= 1) {
        int t = __shfl_up_sync(0xffffffff, incl, o);
        if (lane >= o) incl += t;
    }
    int wtotal = __shfl_sync(0xffffffff, incl, 31);
    int base = 0;
    if (lane == 0) base = atomicAdd(&g_total, wtotal);
    base = __shfl_sync(0xffffffff, base, 0);
    if (n < NN) {
        int pos = base + incl - d;
        g_rowptr[n] = pos;
        g_cursor[n] = pos;
    }
}

__global__ void k_fill(const int* __restrict__ src, const int* __restrict__ dst) {
    int e = blockIdx.x * blockDim.x + threadIdx.x;
    if (e < NE) {
        int pos = atomicAdd(&g_cursor[dst[e]], 1);
        g_csr_src[pos] = src[e];
    }
}

// ---------------- gather-aggregate (CSR, warp per node) ----------------
__global__ void k_gather26(const float* __restrict__ h) {
    int gid = blockIdx.x * blockDim.x + threadIdx.x;
    int n = gid >> 5;
    int c = gid & 31;
    if (n >= NN) return;
    int start = g_rowptr[n];
    int cnt = g_deg_in_i[n];
    if (c < INC) {
        float acc = 0.f;
        int i = 0;
        for (; i + 2 <= cnt; i += 2) {
            int s0 = g_csr_src[start + i];
            int s1 = g_csr_src[start + i + 1];
            acc = fmaf(h[(size_t)s0 * INC + c], g_norm_src[s0], acc);
            acc = fmaf(h[(size_t)s1 * INC + c], g_norm_src[s1], acc);
        }
        if (i < cnt) {
            int s0 = g_csr_src[start + i];
            acc = fmaf(h[(size_t)s0 * INC + c], g_norm_src[s0], acc);
        }
        g_agg[(size_t)n * INC + c] = acc;
    }
}

// pre-scale: g_xh <- half(relu(bn(g_x)) * norm_src[row])
__global__ void k_prescale() {
    int i = blockIdx.x * blockDim.x + threadIdx.x; // over NN*32 float4
    if (i >= NN * (HID / 4)) return;
    int lane = i & 31;
    int row = i >> 5;
    float4 sc = ((const float4*)g_scale)[lane];
    float4 sh = ((const float4*)g_shift)[lane];
    float ns = g_norm_src[row];
    float4 v = ((const float4*)g_x)[i];
    float2 lo = make_float2(fmaxf(fmaf(v.x, sc.x, sh.x), 0.f) * ns,
                            fmaxf(fmaf(v.y, sc.y, sh.y), 0.f) * ns);
    float2 hi = make_float2(fmaxf(fmaf(v.z, sc.z, sh.z), 0.f) * ns,
                            fmaxf(fmaf(v.w, sc.w, sh.w), 0.f) * ns);
    __half2 h0 = __float22half2_rn(lo);
    __half2 h1 = __float22half2_rn(hi);
    uint2 packed;
    packed.x = *(unsigned int*)&h0;
    packed.y = *(unsigned int*)&h1;
    ((uint2*)g_xh)[i] = packed;
}

// pure-sum gather over fp16 pre-scaled activations, fp32 accumulation
__global__ void k_gather128() {
    int gid = blockIdx.x * blockDim.x + threadIdx.x;
    int n = gid >> 5;
    int lane = gid & 31;
    if (n >= NN) return;
    int start = g_rowptr[n];
    int cnt = g_deg_in_i[n];
    float4 acc = make_float4(0.f, 0.f, 0.f, 0.f);
    const uint2* xh = (const uint2*)g_xh;
    int i = 0;
    for (; i + 4 <= cnt; i += 4) {
        int s0 = g_csr_src[start + i];
        int s1 = g_csr_src[start + i + 1];
        int s2 = g_csr_src[start + i + 2];
        int s3 = g_csr_src[start + i + 3];
        uint2 p0 = __ldg(xh + (size_t)s0 * 32 + lane);
        uint2 p1 = __ldg(xh + (size_t)s1 * 32 + lane);
        uint2 p2 = __ldg(xh + (size_t)s2 * 32 + lane);
        uint2 p3 = __ldg(xh + (size_t)s3 * 32 + lane);
        float2 a0 = __half22float2(*(__half2*)&p0.x), b0 = __half22float2(*(__half2*)&p0.y);
        float2 a1 = __half22float2(*(__half2*)&p1.x), b1 = __half22float2(*(__half2*)&p1.y);
        float2 a2 = __half22float2(*(__half2*)&p2.x), b2 = __half22float2(*(__half2*)&p2.y);
        float2 a3 = __half22float2(*(__half2*)&p3.x), b3 = __half22float2(*(__half2*)&p3.y);
        acc.x += (a0.x + a1.x) + (a2.x + a3.x);
        acc.y += (a0.y + a1.y) + (a2.y + a3.y);
        acc.z += (b0.x + b1.x) + (b2.x + b3.x);
        acc.w += (b0.y + b1.y) + (b2.y + b3.y);
    }
    for (; i < cnt; i++) {
        int s0 = g_csr_src[start + i];
        uint2 p0 = __ldg(xh + (size_t)s0 * 32 + lane);
        float2 a0 = __half22float2(*(__half2*)&p0.x), b0 = __half22float2(*(__half2*)&p0.y);
        acc.x += a0.x; acc.y += a0.y; acc.z += b0.x; acc.w += b0.y;
    }
    // agg layout: lane owns channels [4*lane, 4*lane+4)
    ((float4*)(g_agg + (size_t)n * HID))[lane] = acc;
}

// ---------------- GEMMs (with BN stats epilogue) ----------------
__global__ void k_zero_stats() {
    int c = threadIdx.x;
    g_sum[c] = 0.f;
    g_sumsq[c] = 0.f;
}

__global__ void k_gemm_l0(const float* __restrict__ W, const float* __restrict__ b) {
    __shared__ float Wsh[INC * HID];
    __shared__ float xs[8 * INC];
    int c = threadIdx.x; // 0..127
    for (int i = c; i < INC * HID; i += HID) Wsh[i] = W[i];
    float bc = b[c];
    float s = 0.f, ss = 0.f;
    int rbase = blockIdx.x * 64;
    for (int rr = 0; rr < 64; rr += 8) {
        int r = rbase + rr;
        if (r >= NN) break;
        __syncthreads();
        for (int i = c; i < 8 * INC; i += HID) {
            int j = i / INC, k = i - j * INC;
            int gr = r + j;
            xs[i] = (gr < NN) ? g_agg[(size_t)gr * INC + k] : 0.f;
        }
        __syncthreads();
        float acc[8] = {0.f,0.f,0.f,0.f,0.f,0.f,0.f,0.f};
#pragma unroll
        for (int k = 0; k < INC; k++) {
            float w = Wsh[k * HID + c];
#pragma unroll
            for (int j = 0; j < 8; j++) acc[j] = fmaf(xs[j * INC + k], w, acc[j]);
        }
#pragma unroll
        for (int j = 0; j < 8; j++) {
            int gr = r + j;
            if (gr < NN) {
                float y = acc[j] * g_norm_dst[gr] + bc;
                g_x[(size_t)gr * HID + c] = y;
                s += y;
                ss = fmaf(y, y, ss);
            }
        }
    }
    atomicAdd(&g_sum[c], s);
    atomicAdd(&g_sumsq[c], ss);
}

#define GEMMH_SMEM ((HID * HID + 8 * HID) * 4)
__global__ void k_gemm_h(const float* __restrict__ W, const float* __restrict__ b) {
    extern __shared__ float smemf[];
    float* Wsh = smemf;
    float* xs = smemf + HID * HID;
    int c = threadIdx.x;
    for (int i = c; i < HID * HID; i += HID) Wsh[i] = W[i];
    float bc = b[c];
    float s = 0.f, ss = 0.f;
    int rbase = blockIdx.x * 64;
    for (int rr = 0; rr < 64; rr += 8) {
        int r = rbase + rr;
        if (r >= NN) break;
        __syncthreads();
#pragma unroll
        for (int j = 0; j < 8; j++) {
            int gr = r + j;
            xs[j * HID + c] = (gr < NN) ? g_agg[(size_t)gr * HID + c] : 0.f;
        }
        __syncthreads();
        float acc[8] = {0.f,0.f,0.f,0.f,0.f,0.f,0.f,0.f};
        const float4* xv = (const float4*)xs;
#pragma unroll 4
        for (int k4 = 0; k4 < 32; k4++) {
            float w0 = Wsh[(k4 * 4 + 0) * HID + c];
            float w1 = Wsh[(k4 * 4 + 1) * HID + c];
            float w2 = Wsh[(k4 * 4 + 2) * HID + c];
            float w3 = Wsh[(k4 * 4 + 3) * HID + c];
#pragma unroll
            for (int j = 0; j < 8; j++) {
                float4 x4 = xv[j * 32 + k4];
                acc[j] = fmaf(x4.x, w0, acc[j]);
                acc[j] = fmaf(x4.y, w1, acc[j]);
                acc[j] = fmaf(x4.z, w2, acc[j]);
                acc[j] = fmaf(x4.w, w3, acc[j]);
            }
        }
#pragma unroll
        for (int j = 0; j < 8; j++) {
            int gr = r + j;
            if (gr < NN) {
                float y = acc[j] * g_norm_dst[gr] + bc;
                g_x[(size_t)gr * HID + c] = y;
                s += y;
                ss = fmaf(y, y, ss);
            }
        }
    }
    atomicAdd(&g_sum[c], s);
    atomicAdd(&g_sumsq[c], ss);
}

__global__ void k_bnfinal(const float* __restrict__ g, const float* __restrict__ bt) {
    int c = threadIdx.x;
    float inv_n = 1.f / (float)NN;
    float mu = g_sum[c] * inv_n;
    float var = g_sumsq[c] * inv_n - mu * mu;
    float sc = g[c] * rsqrtf(var + BN_EPS);
    g_scale[c] = sc;
    g_shift[c] = bt[c] - mu * sc;
}

// final FC: applies BN2 + ReLU on load, then [NN,128]@[128,64]+bfc -> d_out
__global__ void k_fc(const float* __restrict__ W, const float* __restrict__ b,
                     float* __restrict__ out) {
    __shared__ float Wsh[HID * OUTC];
    __shared__ float xs[8 * HID];
    __shared__ float scs[HID], shs[HID];
    int c = threadIdx.x; // 0..63
    for (int i = c; i < HID * OUTC; i += OUTC) Wsh[i] = W[i];
    for (int i = c; i < HID; i += OUTC) { scs[i] = g_scale[i]; shs[i] = g_shift[i]; }
    float bc = b[c];
    int rbase = blockIdx.x * 64;
    for (int rr = 0; rr < 64; rr += 8) {
        int r = rbase + rr;
        if (r >= NN) break;
        __syncthreads();
        for (int i = c; i < 8 * HID; i += OUTC) {
            int j = i >> 7, k = i & 127;
            int gr = r + j;
            float v = (gr < NN) ? g_x[(size_t)gr * HID + k] : 0.f;
            xs[i] = fmaxf(fmaf(v, scs[k], shs[k]), 0.f);
        }
        __syncthreads();
        float acc[8] = {0.f,0.f,0.f,0.f,0.f,0.f,0.f,0.f};
        const float4* xv = (const float4*)xs;
#pragma unroll 4
        for (int k4 = 0; k4 < 32; k4++) {
            float w0 = Wsh[(k4 * 4 + 0) * OUTC + c];
            float w1 = Wsh[(k4 * 4 + 1) * OUTC + c];
            float w2 = Wsh[(k4 * 4 + 2) * OUTC + c];
            float w3 = Wsh[(k4 * 4 + 3) * OUTC + c];
#pragma unroll
            for (int j = 0; j < 8; j++) {
                float4 x4 = xv[j * 32 + k4];
                acc[j] = fmaf(x4.x, w0, acc[j]);
                acc[j] = fmaf(x4.y, w1, acc[j]);
                acc[j] = fmaf(x4.z, w2, acc[j]);
                acc[j] = fmaf(x4.w, w3, acc[j]);
            }
        }
#pragma unroll
        for (int j = 0; j < 8; j++) {
            int gr = r + j;
            if (gr < NN) out[(size_t)gr * OUTC + c] = acc[j] + bc;
        }
    }
}

// ---------------- launch ----------------
extern "C" void kernel_launch(void* const* d_in, const int* in_sizes, int n_in,
                              void* d_out, int out_size) {
    const float* h   = (const float*)d_in[0];
    const int*   src = (const int*)d_in[1];
    const int*   dst = (const int*)d_in[2];
    const float* w0  = (const float*)d_in[3];
    const float* b0  = (const float*)d_in[4];
    const float* w1  = (const float*)d_in[5];
    const float* b1  = (const float*)d_in[6];
    const float* w2  = (const float*)d_in[7];
    const float* b2  = (const float*)d_in[8];
    const float* g0  = (const float*)d_in[9];
    const float* bt0 = (const float*)d_in[10];
    const float* g1  = (const float*)d_in[11];
    const float* bt1 = (const float*)d_in[12];
    const float* g2  = (const float*)d_in[13];
    const float* bt2 = (const float*)d_in[14];
    const float* wfc = (const float*)d_in[15];
    const float* bfc = (const float*)d_in[16];
    float* out = (float*)d_out;

    cudaFuncSetAttribute(k_gemm_h, cudaFuncAttributeMaxDynamicSharedMemorySize, GEMMH_SMEM);

    // graph prep: degrees, norms, node weights, CSR
    k_zero_deg<<<(NN + 255) / 256, 256>>>();
    k_degrees<<<(NE + 255) / 256, 256>>>(src, dst);
    k_nodeprep<<<(NN + 255) / 256, 256>>>(h, out);
    k_alloc<<<(NN + 255) / 256, 256>>>();
    k_fill<<<(NE + 255) / 256, 256>>>(src, dst);

    // ---- layer 0 (26 -> 128) ----
    k_gather26<<<(NN * 32 + 255) / 256, 256>>>(h);
    k_zero_stats<<<1, HID>>>();
    k_gemm_l0<<<(NN + 63) / 64, 128>>>(w0, b0);
    k_bnfinal<<<1, HID>>>(g0, bt0);

    // ---- layers 1, 2 (128 -> 128) ----
    const float* Ws[2]  = {w1, w2};
    const float* bs[2]  = {b1, b2};
    const float* gs[2]  = {g1, g2};
    const float* bts[2] = {bt1, bt2};
    for (int l = 0; l < 2; l++) {
        k_prescale<<<(NN * (HID / 4) + 255) / 256, 256>>>();
        k_gather128<<<(NN * 32 + 255) / 256, 256>>>();
        k_zero_stats<<<1, HID>>>();
        k_gemm_h<<<(NN + 63) / 64, 128, GEMMH_SMEM>>>(Ws[l], bs[l]);
        k_bnfinal<<<1, HID>>>(gs[l], bts[l]);
    }

    // ---- final FC (128 -> 64), BN2+ReLU fused into load ----
    k_fc<<<(NN + 63) / 64, 64>>>(wfc, bfc, out);
}

// round 5
// speedup vs baseline: 2.0760x; 1.2310x over previous
#include <cuda_runtime.h>
#include <cuda_fp16.h>

#define NN   100000
#define NE   1600000
#define INC  26
#define HID  128
#define OUTC 64
#define BN_EPS 1e-5f
#define OUT_ELEMS (NN * OUTC)

// ---------------- device scratch ----------------
__device__ float  g_x[NN * HID];    // raw (pre-BN) layer outputs, fp32
__device__ __half g_xh[NN * HID];   // pre-scaled activations, fp16 (gather input)
__device__ float  g_agg[NN * HID];  // gather accumulator (layer0 uses NN*26)
__device__ float  g_norm_src[NN];
__device__ float  g_norm_dst[NN];
__device__ int    g_deg_out_i[NN];
__device__ int    g_deg_in_i[NN];
__device__ int    g_rowptr[NN];
__device__ int    g_cursor[NN];
__device__ int    g_csr_src[NE];
__device__ int    g_total;
__device__ float  g_sum[HID];
__device__ float  g_sumsq[HID];
__device__ float  g_scale[HID];
__device__ float  g_shift[HID];

__constant__ float c_wtable[26] = {
    0.7f,0.9f,0.7f,0.9f,0.3f,0.7f,0.3f,0.9f,0.3f,0.3f,0.9f,0.7f,0.1f,
    0.9f,0.5f,0.9f,0.5f,0.5f,0.1f,0.3f,0.7f,0.9f,0.9f,0.9f,0.9f,0.9f};

// ---------------- prep kernels ----------------
__global__ void k_zero_deg() {
    int n = blockIdx.x * blockDim.x + threadIdx.x;
    if (n < NN) { g_deg_out_i[n] = 0; g_deg_in_i[n] = 0; }
    if (n == 0) g_total = 0;
}

__global__ void k_degrees(const int* __restrict__ src, const int* __restrict__ dst) {
    int e = blockIdx.x * blockDim.x + threadIdx.x;
    if (e < NE) {
        atomicAdd(&g_deg_out_i[src[e]], 1);
        atomicAdd(&g_deg_in_i[dst[e]], 1);
    }
}

__global__ void k_nodeprep(const float* __restrict__ h, float* __restrict__ out) {
    int n = blockIdx.x * blockDim.x + threadIdx.x;
    if (n >= NN) return;
    const float* hr = h + (size_t)n * INC;
    float best = hr[0];
    int bi = 0;
#pragma unroll
    for (int c = 1; c < INC; c++) {
        float v = hr[c];
        if (v > best) { best = v; bi = c; }
    }
    out[OUT_ELEMS + n] = c_wtable[bi];
    g_norm_src[n] = rsqrtf(fmaxf((float)g_deg_out_i[n], 1.f));
    g_norm_dst[n] = rsqrtf(fmaxf((float)g_deg_in_i[n], 1.f));
}

// warp-aggregated segment allocator (node order irrelevant for the gather)
__global__ void k_alloc() {
    int n = blockIdx.x * blockDim.x + threadIdx.x;
    int lane = threadIdx.x & 31;
    int d = (n < NN) ? g_deg_in_i[n] : 0;
    int incl = d;
#pragma unroll
    for (int o = 1; o < 32; o <<= 1) {
        int t = __shfl_up_sync(0xffffffff, incl, o);
        if (lane >= o) incl += t;
    }
    int wtotal = __shfl_sync(0xffffffff, incl, 31);
    int base = 0;
    if (lane == 0) base = atomicAdd(&g_total, wtotal);
    base = __shfl_sync(0xffffffff, base, 0);
    if (n < NN) {
        int pos = base + incl - d;
        g_rowptr[n] = pos;
        g_cursor[n] = pos;
    }
}

__global__ void k_fill(const int* __restrict__ src, const int* __restrict__ dst) {
    int e = blockIdx.x * blockDim.x + threadIdx.x;
    if (e < NE) {
        int pos = atomicAdd(&g_cursor[dst[e]], 1);
        g_csr_src[pos] = src[e];
    }
}

// ---------------- gather-aggregate (CSR, warp per node) ----------------
__global__ void k_gather26(const float* __restrict__ h) {
    int gid = blockIdx.x * blockDim.x + threadIdx.x;
    int n = gid >> 5;
    int c = gid & 31;
    if (n >= NN) return;
    int start = g_rowptr[n];
    int cnt = g_deg_in_i[n];
    if (c < INC) {
        float acc = 0.f;
        int i = 0;
        for (; i + 2 <= cnt; i += 2) {
            int s0 = g_csr_src[start + i];
            int s1 = g_csr_src[start + i + 1];
            acc = fmaf(h[(size_t)s0 * INC + c], g_norm_src[s0], acc);
            acc = fmaf(h[(size_t)s1 * INC + c], g_norm_src[s1], acc);
        }
        if (i < cnt) {
            int s0 = g_csr_src[start + i];
            acc = fmaf(h[(size_t)s0 * INC + c], g_norm_src[s0], acc);
        }
        g_agg[(size_t)n * INC + c] = acc;
    }
}

// pre-scale: g_xh <- half(relu(bn(g_x)) * norm_src[row])
__global__ void k_prescale() {
    int i = blockIdx.x * blockDim.x + threadIdx.x; // over NN*32 float4
    if (i >= NN * (HID / 4)) return;
    int lane = i & 31;
    int row = i >> 5;
    float4 sc = ((const float4*)g_scale)[lane];
    float4 sh = ((const float4*)g_shift)[lane];
    float ns = g_norm_src[row];
    float4 v = ((const float4*)g_x)[i];
    float2 lo = make_float2(fmaxf(fmaf(v.x, sc.x, sh.x), 0.f) * ns,
                            fmaxf(fmaf(v.y, sc.y, sh.y), 0.f) * ns);
    float2 hi = make_float2(fmaxf(fmaf(v.z, sc.z, sh.z), 0.f) * ns,
                            fmaxf(fmaf(v.w, sc.w, sh.w), 0.f) * ns);
    __half2 h0 = __float22half2_rn(lo);
    __half2 h1 = __float22half2_rn(hi);
    uint2 packed;
    packed.x = *(unsigned int*)&h0;
    packed.y = *(unsigned int*)&h1;
    ((uint2*)g_xh)[i] = packed;
}

// pure-sum gather over fp16 pre-scaled activations, fp32 accumulation, MLP=8
__global__ void k_gather128() {
    int gid = blockIdx.x * blockDim.x + threadIdx.x;
    int n = gid >> 5;
    int lane = gid & 31;
    if (n >= NN) return;
    int start = g_rowptr[n];
    int cnt = g_deg_in_i[n];
    float4 acc = make_float4(0.f, 0.f, 0.f, 0.f);
    const uint2* xh = (const uint2*)g_xh;
    const int* cs = g_csr_src + start;
    int i = 0;
    for (; i + 8 <= cnt; i += 8) {
        int s0 = cs[i + 0], s1 = cs[i + 1], s2 = cs[i + 2], s3 = cs[i + 3];
        int s4 = cs[i + 4], s5 = cs[i + 5], s6 = cs[i + 6], s7 = cs[i + 7];
        uint2 p0 = __ldg(xh + (size_t)s0 * 32 + lane);
        uint2 p1 = __ldg(xh + (size_t)s1 * 32 + lane);
        uint2 p2 = __ldg(xh + (size_t)s2 * 32 + lane);
        uint2 p3 = __ldg(xh + (size_t)s3 * 32 + lane);
        uint2 p4 = __ldg(xh + (size_t)s4 * 32 + lane);
        uint2 p5 = __ldg(xh + (size_t)s5 * 32 + lane);
        uint2 p6 = __ldg(xh + (size_t)s6 * 32 + lane);
        uint2 p7 = __ldg(xh + (size_t)s7 * 32 + lane);
        float2 a, bb;
#define ACC(P) \
        a = __half22float2(*(__half2*)&P.x); bb = __half22float2(*(__half2*)&P.y); \
        acc.x += a.x; acc.y += a.y; acc.z += bb.x; acc.w += bb.y;
        ACC(p0) ACC(p1) ACC(p2) ACC(p3) ACC(p4) ACC(p5) ACC(p6) ACC(p7)
    }
    for (; i + 2 <= cnt; i += 2) {
        int s0 = cs[i], s1 = cs[i + 1];
        uint2 p0 = __ldg(xh + (size_t)s0 * 32 + lane);
        uint2 p1 = __ldg(xh + (size_t)s1 * 32 + lane);
        float2 a, bb;
        ACC(p0) ACC(p1)
    }
    if (i < cnt) {
        int s0 = cs[i];
        uint2 p0 = __ldg(xh + (size_t)s0 * 32 + lane);
        float2 a, bb;
        ACC(p0)
    }
#undef ACC
    ((float4*)(g_agg + (size_t)n * HID))[lane] = acc;
}

// ---------------- GEMMs (with BN stats epilogue) ----------------
__global__ void k_zero_stats() {
    int c = threadIdx.x;
    g_sum[c] = 0.f;
    g_sumsq[c] = 0.f;
}

__global__ void k_gemm_l0(const float* __restrict__ W, const float* __restrict__ b) {
    __shared__ float Wsh[INC * HID];
    __shared__ float xs[8 * INC];
    int c = threadIdx.x; // 0..127
    for (int i = c; i < INC * HID; i += HID) Wsh[i] = W[i];
    float bc = b[c];
    float s = 0.f, ss = 0.f;
    int rbase = blockIdx.x * 64;
    for (int rr = 0; rr < 64; rr += 8) {
        int r = rbase + rr;
        if (r >= NN) break;
        __syncthreads();
        for (int i = c; i < 8 * INC; i += HID) {
            int j = i / INC, k = i - j * INC;
            int gr = r + j;
            xs[i] = (gr < NN) ? g_agg[(size_t)gr * INC + k] : 0.f;
        }
        __syncthreads();
        float acc[8] = {0.f,0.f,0.f,0.f,0.f,0.f,0.f,0.f};
#pragma unroll
        for (int k = 0; k < INC; k++) {
            float w = Wsh[k * HID + c];
#pragma unroll
            for (int j = 0; j < 8; j++) acc[j] = fmaf(xs[j * INC + k], w, acc[j]);
        }
#pragma unroll
        for (int j = 0; j < 8; j++) {
            int gr = r + j;
            if (gr < NN) {
                float y = acc[j] * g_norm_dst[gr] + bc;
                g_x[(size_t)gr * HID + c] = y;
                s += y;
                ss = fmaf(y, y, ss);
            }
        }
    }
    atomicAdd(&g_sum[c], s);
    atomicAdd(&g_sumsq[c], ss);
}

// hidden GEMM v2: 128 threads; lane owns 4 cols, warp owns 8 rows per 32-row tile
#define GH2_SMEM ((HID * HID + 32 * HID) * 4)
#define GH2_GRID 296
__global__ void __launch_bounds__(128, 2) k_gemm_h2(const float* __restrict__ W,
                                                    const float* __restrict__ b) {
    extern __shared__ float sm[];
    float* Wsh = sm;               // 128*128 floats (64KB)
    float* xs  = sm + HID * HID;   // 32*128 floats (16KB)
    int tid = threadIdx.x;
    int lane = tid & 31, warp = tid >> 5;
    // stage W (vectorized, coalesced)
    {
        const float4* Wv = (const float4*)W;
        float4* Wsv = (float4*)Wsh;
        for (int i = tid; i < HID * HID / 4; i += 128) Wsv[i] = Wv[i];
    }
    float4 bc = ((const float4*)b)[lane];
    float s4[4] = {0.f,0.f,0.f,0.f};
    float q4[4] = {0.f,0.f,0.f,0.f};
    const float4* Wsv = (const float4*)Wsh;

    for (int rb = blockIdx.x * 32; rb < NN; rb += GH2_GRID * 32) {
        __syncthreads();
        {   // stage 32 rows of g_agg (NN % 32 == 0, no tail)
            const float4* srcv = (const float4*)(g_agg + (size_t)rb * HID);
            float4* xv = (float4*)xs;
            for (int i = tid; i < 32 * (HID / 4); i += 128) xv[i] = srcv[i];
        }
        __syncthreads();
        int r0 = warp * 8;
        float acc[8][4];
#pragma unroll
        for (int j = 0; j < 8; j++) { acc[j][0]=0.f; acc[j][1]=0.f; acc[j][2]=0.f; acc[j][3]=0.f; }
#pragma unroll 8
        for (int k4 = 0; k4 < 32; k4++) {
            float4 wa = Wsv[(k4 * 4 + 0) * 32 + lane];
            float4 wb = Wsv[(k4 * 4 + 1) * 32 + lane];
            float4 wc = Wsv[(k4 * 4 + 2) * 32 + lane];
            float4 wd = Wsv[(k4 * 4 + 3) * 32 + lane];
#pragma unroll
            for (int j = 0; j < 8; j++) {
                float4 x4 = ((const float4*)(xs + (r0 + j) * HID))[k4];
                acc[j][0] = fmaf(x4.x, wa.x, acc[j][0]);
                acc[j][1] = fmaf(x4.x, wa.y, acc[j][1]);
                acc[j][2] = fmaf(x4.x, wa.z, acc[j][2]);
                acc[j][3] = fmaf(x4.x, wa.w, acc[j][3]);
                acc[j][0] = fmaf(x4.y, wb.x, acc[j][0]);
                acc[j][1] = fmaf(x4.y, wb.y, acc[j][1]);
                acc[j][2] = fmaf(x4.y, wb.z, acc[j][2]);
                acc[j][3] = fmaf(x4.y, wb.w, acc[j][3]);
                acc[j][0] = fmaf(x4.z, wc.x, acc[j][0]);
                acc[j][1] = fmaf(x4.z, wc.y, acc[j][1]);
                acc[j][2] = fmaf(x4.z, wc.z, acc[j][2]);
                acc[j][3] = fmaf(x4.z, wc.w, acc[j][3]);
                acc[j][0] = fmaf(x4.w, wd.x, acc[j][0]);
                acc[j][1] = fmaf(x4.w, wd.y, acc[j][1]);
                acc[j][2] = fmaf(x4.w, wd.z, acc[j][2]);
                acc[j][3] = fmaf(x4.w, wd.w, acc[j][3]);
            }
        }
#pragma unroll
        for (int j = 0; j < 8; j++) {
            int gr = rb + r0 + j;
            float nd = g_norm_dst[gr];
            float4 y;
            y.x = acc[j][0] * nd + bc.x;
            y.y = acc[j][1] * nd + bc.y;
            y.z = acc[j][2] * nd + bc.z;
            y.w = acc[j][3] * nd + bc.w;
            ((float4*)(g_x + (size_t)gr * HID))[lane] = y;
            s4[0] += y.x; q4[0] = fmaf(y.x, y.x, q4[0]);
            s4[1] += y.y; q4[1] = fmaf(y.y, y.y, q4[1]);
            s4[2] += y.z; q4[2] = fmaf(y.z, y.z, q4[2]);
            s4[3] += y.w; q4[3] = fmaf(y.w, y.w, q4[3]);
        }
    }
#pragma unroll
    for (int t = 0; t < 4; t++) {
        atomicAdd(&g_sum[lane * 4 + t], s4[t]);
        atomicAdd(&g_sumsq[lane * 4 + t], q4[t]);
    }
}

__global__ void k_bnfinal(const float* __restrict__ g, const float* __restrict__ bt) {
    int c = threadIdx.x;
    float inv_n = 1.f / (float)NN;
    float mu = g_sum[c] * inv_n;
    float var = g_sumsq[c] * inv_n - mu * mu;
    float sc = g[c] * rsqrtf(var + BN_EPS);
    g_scale[c] = sc;
    g_shift[c] = bt[c] - mu * sc;
}

// final FC: applies BN2 + ReLU on load, then [NN,128]@[128,64]+bfc -> d_out
__global__ void k_fc(const float* __restrict__ W, const float* __restrict__ b,
                     float* __restrict__ out) {
    __shared__ float Wsh[HID * OUTC];
    __shared__ float xs[8 * HID];
    __shared__ float scs[HID], shs[HID];
    int c = threadIdx.x; // 0..63
    for (int i = c; i < HID * OUTC; i += OUTC) Wsh[i] = W[i];
    for (int i = c; i < HID; i += OUTC) { scs[i] = g_scale[i]; shs[i] = g_shift[i]; }
    float bc = b[c];
    int rbase = blockIdx.x * 64;
    for (int rr = 0; rr < 64; rr += 8) {
        int r = rbase + rr;
        if (r >= NN) break;
        __syncthreads();
        for (int i = c; i < 8 * HID; i += OUTC) {
            int j = i >> 7, k = i & 127;
            int gr = r + j;
            float v = (gr < NN) ? g_x[(size_t)gr * HID + k] : 0.f;
            xs[i] = fmaxf(fmaf(v, scs[k], shs[k]), 0.f);
        }
        __syncthreads();
        float acc[8] = {0.f,0.f,0.f,0.f,0.f,0.f,0.f,0.f};
        const float4* xv = (const float4*)xs;
#pragma unroll 4
        for (int k4 = 0; k4 < 32; k4++) {
            float w0 = Wsh[(k4 * 4 + 0) * OUTC + c];
            float w1 = Wsh[(k4 * 4 + 1) * OUTC + c];
            float w2 = Wsh[(k4 * 4 + 2) * OUTC + c];
            float w3 = Wsh[(k4 * 4 + 3) * OUTC + c];
#pragma unroll
            for (int j = 0; j < 8; j++) {
                float4 x4 = xv[j * 32 + k4];
                acc[j] = fmaf(x4.x, w0, acc[j]);
                acc[j] = fmaf(x4.y, w1, acc[j]);
                acc[j] = fmaf(x4.z, w2, acc[j]);
                acc[j] = fmaf(x4.w, w3, acc[j]);
            }
        }
#pragma unroll
        for (int j = 0; j < 8; j++) {
            int gr = r + j;
            if (gr < NN) out[(size_t)gr * OUTC + c] = acc[j] + bc;
        }
    }
}

// ---------------- launch ----------------
extern "C" void kernel_launch(void* const* d_in, const int* in_sizes, int n_in,
                              void* d_out, int out_size) {
    const float* h   = (const float*)d_in[0];
    const int*   src = (const int*)d_in[1];
    const int*   dst = (const int*)d_in[2];
    const float* w0  = (const float*)d_in[3];
    const float* b0  = (const float*)d_in[4];
    const float* w1  = (const float*)d_in[5];
    const float* b1  = (const float*)d_in[6];
    const float* w2  = (const float*)d_in[7];
    const float* b2  = (const float*)d_in[8];
    const float* g0  = (const float*)d_in[9];
    const float* bt0 = (const float*)d_in[10];
    const float* g1  = (const float*)d_in[11];
    const float* bt1 = (const float*)d_in[12];
    const float* g2  = (const float*)d_in[13];
    const float* bt2 = (const float*)d_in[14];
    const float* wfc = (const float*)d_in[15];
    const float* bfc = (const float*)d_in[16];
    float* out = (float*)d_out;

    cudaFuncSetAttribute(k_gemm_h2, cudaFuncAttributeMaxDynamicSharedMemorySize, GH2_SMEM);

    // graph prep: degrees, norms, node weights, CSR
    k_zero_deg<<<(NN + 255) / 256, 256>>>();
    k_degrees<<<(NE + 255) / 256, 256>>>(src, dst);
    k_nodeprep<<<(NN + 255) / 256, 256>>>(h, out);
    k_alloc<<<(NN + 255) / 256, 256>>>();
    k_fill<<<(NE + 255) / 256, 256>>>(src, dst);

    // ---- layer 0 (26 -> 128) ----
    k_gather26<<<(NN * 32 + 255) / 256, 256>>>(h);
    k_zero_stats<<<1, HID>>>();
    k_gemm_l0<<<(NN + 63) / 64, 128>>>(w0, b0);
    k_bnfinal<<<1, HID>>>(g0, bt0);

    // ---- layers 1, 2 (128 -> 128) ----
    const float* Ws[2]  = {w1, w2};
    const float* bs[2]  = {b1, b2};
    const float* gs[2]  = {g1, g2};
    const float* bts[2] = {bt1, bt2};
    for (int l = 0; l < 2; l++) {
        k_prescale<<<(NN * (HID / 4) + 255) / 256, 256>>>();
        k_gather128<<<(NN * 32 + 255) / 256, 256>>>();
        k_zero_stats<<<1, HID>>>();
        k_gemm_h2<<<GH2_GRID, 128, GH2_SMEM>>>(Ws[l], bs[l]);
        k_bnfinal<<<1, HID>>>(gs[l], bts[l]);
    }

    // ---- final FC (128 -> 64), BN2+ReLU fused into load ----
    k_fc<<<(NN + 63) / 64, 64>>>(wfc, bfc, out);
}

// round 7
// speedup vs baseline: 2.1949x; 1.0573x over previous
#include <cuda_runtime.h>
#include <cuda_fp16.h>

#define NN   100000
#define NE   1600000
#define INC  26
#define HID  128
#define OUTC 64
#define BN_EPS 1e-5f
#define OUT_ELEMS (NN * OUTC)

// ---------------- device scratch ----------------
__device__ float  g_x[NN * HID];    // raw (pre-BN) layer outputs, fp32
__device__ __half g_xh[NN * HID];   // pre-scaled activations, fp16 (gather input)
__device__ __half g_h16[NN * 32];   // layer-0 messages: half(h * norm_src), padded to 32ch
__device__ float  g_agg[NN * HID];  // gather accumulator (layer0 uses NN*32 padded)
__device__ float  g_norm_src[NN];
__device__ float  g_norm_dst[NN];
__device__ int    g_deg_out_i[NN];
__device__ int    g_deg_in_i[NN];
__device__ int    g_rowptr[NN];
__device__ int    g_cursor[NN];
__device__ int    g_csr_src[NE];
__device__ int    g_total;
__device__ float  g_sum[HID];
__device__ float  g_sumsq[HID];
__device__ float  g_scale[HID];
__device__ float  g_shift[HID];

__constant__ float c_wtable[26] = {
    0.7f,0.9f,0.7f,0.9f,0.3f,0.7f,0.3f,0.9f,0.3f,0.3f,0.9f,0.7f,0.1f,
    0.9f,0.5f,0.9f,0.5f,0.5f,0.1f,0.3f,0.7f,0.9f,0.9f,0.9f,0.9f,0.9f};

// ---------------- prep kernels ----------------
__global__ void k_zero_deg() {
    int n = blockIdx.x * blockDim.x + threadIdx.x;
    if (n < NN) { g_deg_out_i[n] = 0; g_deg_in_i[n] = 0; }
    if (n == 0) g_total = 0;
}

__global__ void k_degrees(const int* __restrict__ src, const int* __restrict__ dst) {
    int e = blockIdx.x * blockDim.x + threadIdx.x;
    if (e < NE) {
        atomicAdd(&g_deg_out_i[src[e]], 1);
        atomicAdd(&g_deg_in_i[dst[e]], 1);
    }
}

// argmax weight + degree norms + fp16-packed, norm_src-scaled layer-0 messages
__global__ void k_nodeprep(const float* __restrict__ h, float* __restrict__ out) {
    int n = blockIdx.x * blockDim.x + threadIdx.x;
    if (n >= NN) return;
    const float* hr = h + (size_t)n * INC;
    float hv[INC];
    float best = -1e30f;
    int bi = 0;
#pragma unroll
    for (int c = 0; c < INC; c++) {
        float v = hr[c];
        hv[c] = v;
        if (v > best) { best = v; bi = c; }
    }
    out[OUT_ELEMS + n] = c_wtable[bi];
    float ns = rsqrtf(fmaxf((float)g_deg_out_i[n], 1.f));
    g_norm_src[n] = ns;
    g_norm_dst[n] = rsqrtf(fmaxf((float)g_deg_in_i[n], 1.f));
    unsigned int* dsth = (unsigned int*)g_h16 + (size_t)n * 16;
#pragma unroll
    for (int j = 0; j < 13; j++) {
        __half2 p = __floats2half2_rn(hv[2 * j] * ns, hv[2 * j + 1] * ns);
        dsth[j] = *(unsigned int*)&p;
    }
    dsth[13] = 0; dsth[14] = 0; dsth[15] = 0;
}

// warp-aggregated segment allocator (node order irrelevant for the gather)
__global__ void k_alloc() {
    int n = blockIdx.x * blockDim.x + threadIdx.x;
    int lane = threadIdx.x & 31;
    int d = (n < NN) ? g_deg_in_i[n] : 0;
    int incl = d;
#pragma unroll
    for (int o = 1; o < 32; o <<= 1) {
        int t = __shfl_up_sync(0xffffffff, incl, o);
        if (lane >= o) incl += t;
    }
    int wtotal = __shfl_sync(0xffffffff, incl, 31);
    int base = 0;
    if (lane == 0) base = atomicAdd(&g_total, wtotal);
    base = __shfl_sync(0xffffffff, base, 0);
    if (n < NN) {
        int pos = base + incl - d;
        g_rowptr[n] = pos;
        g_cursor[n] = pos;
    }
}

__global__ void k_fill(const int* __restrict__ src, const int* __restrict__ dst) {
    int e = blockIdx.x * blockDim.x + threadIdx.x;
    if (e < NE) {
        int pos = atomicAdd(&g_cursor[dst[e]], 1);
        g_csr_src[pos] = src[e];
    }
}

// ---------------- layer-0 gather: fp16 packed rows, half-warp per edge ----------------
__global__ void k_gather26() {
    int gid = blockIdx.x * blockDim.x + threadIdx.x;
    int n = gid >> 5;
    int lane = gid & 31;
    if (n >= NN) return;
    int sub = lane & 15;   // channel pair index (2 ch each)
    int w = lane >> 4;     // which edge of the pair
    int start = g_rowptr[n];
    int cnt = g_deg_in_i[n];
    const int* cs = g_csr_src + start;
    const unsigned int* xh = (const unsigned int*)g_h16;
    float2 acc = make_float2(0.f, 0.f);
    int i = 0;
    for (; i + 4 <= cnt; i += 4) {
        int sA = cs[i + w];
        int sB = cs[i + 2 + w];
        unsigned int pA = __ldg(xh + (size_t)sA * 16 + sub);
        unsigned int pB = __ldg(xh + (size_t)sB * 16 + sub);
        float2 a = __half22float2(*(__half2*)&pA);
        float2 b = __half22float2(*(__half2*)&pB);
        acc.x += a.x + b.x;
        acc.y += a.y + b.y;
    }
    for (; i < cnt; i += 2) {
        int e = i + w;
        if (e < cnt) {
            int s = cs[e];
            unsigned int p = __ldg(xh + (size_t)s * 16 + sub);
            float2 a = __half22float2(*(__half2*)&p);
            acc.x += a.x;
            acc.y += a.y;
        }
    }
    acc.x += __shfl_xor_sync(0xffffffff, acc.x, 16);
    acc.y += __shfl_xor_sync(0xffffffff, acc.y, 16);
    if (w == 0 && sub < 13) {
        ((float2*)(g_agg + (size_t)n * 32))[sub] = acc;
    }
}

// pre-scale: g_xh <- half(relu(bn(g_x)) * norm_src[row])
__global__ void k_prescale() {
    int i = blockIdx.x * blockDim.x + threadIdx.x; // over NN*32 float4
    if (i >= NN * (HID / 4)) return;
    int lane = i & 31;
    int row = i >> 5;
    float4 sc = ((const float4*)g_scale)[lane];
    float4 sh = ((const float4*)g_shift)[lane];
    float ns = g_norm_src[row];
    float4 v = ((const float4*)g_x)[i];
    float2 lo = make_float2(fmaxf(fmaf(v.x, sc.x, sh.x), 0.f) * ns,
                            fmaxf(fmaf(v.y, sc.y, sh.y), 0.f) * ns);
    float2 hi = make_float2(fmaxf(fmaf(v.z, sc.z, sh.z), 0.f) * ns,
                            fmaxf(fmaf(v.w, sc.w, sh.w), 0.f) * ns);
    __half2 h0 = __float22half2_rn(lo);
    __half2 h1 = __float22half2_rn(hi);
    uint2 packed;
    packed.x = *(unsigned int*)&h0;
    packed.y = *(unsigned int*)&h1;
    ((uint2*)g_xh)[i] = packed;
}

// pure-sum gather over fp16 pre-scaled activations, fp32 accumulation, MLP=8
__global__ void k_gather128() {
    int gid = blockIdx.x * blockDim.x + threadIdx.x;
    int n = gid >> 5;
    int lane = gid & 31;
    if (n >= NN) return;
    int start = g_rowptr[n];
    int cnt = g_deg_in_i[n];
    float4 acc = make_float4(0.f, 0.f, 0.f, 0.f);
    const uint2* xh = (const uint2*)g_xh;
    const int* cs = g_csr_src + start;
    int i = 0;
    for (; i + 8 <= cnt; i += 8) {
        int s0 = cs[i + 0], s1 = cs[i + 1], s2 = cs[i + 2], s3 = cs[i + 3];
        int s4 = cs[i + 4], s5 = cs[i + 5], s6 = cs[i + 6], s7 = cs[i + 7];
        uint2 p0 = __ldg(xh + (size_t)s0 * 32 + lane);
        uint2 p1 = __ldg(xh + (size_t)s1 * 32 + lane);
        uint2 p2 = __ldg(xh + (size_t)s2 * 32 + lane);
        uint2 p3 = __ldg(xh + (size_t)s3 * 32 + lane);
        uint2 p4 = __ldg(xh + (size_t)s4 * 32 + lane);
        uint2 p5 = __ldg(xh + (size_t)s5 * 32 + lane);
        uint2 p6 = __ldg(xh + (size_t)s6 * 32 + lane);
        uint2 p7 = __ldg(xh + (size_t)s7 * 32 + lane);
        float2 a, bb;
#define ACC(P) \
        a = __half22float2(*(__half2*)&P.x); bb = __half22float2(*(__half2*)&P.y); \
        acc.x += a.x; acc.y += a.y; acc.z += bb.x; acc.w += bb.y;
        ACC(p0) ACC(p1) ACC(p2) ACC(p3) ACC(p4) ACC(p5) ACC(p6) ACC(p7)
    }
    for (; i + 2 <= cnt; i += 2) {
        int s0 = cs[i], s1 = cs[i + 1];
        uint2 p0 = __ldg(xh + (size_t)s0 * 32 + lane);
        uint2 p1 = __ldg(xh + (size_t)s1 * 32 + lane);
        float2 a, bb;
        ACC(p0) ACC(p1)
    }
    if (i < cnt) {
        int s0 = cs[i];
        uint2 p0 = __ldg(xh + (size_t)s0 * 32 + lane);
        float2 a, bb;
        ACC(p0)
    }
#undef ACC
    ((float4*)(g_agg + (size_t)n * HID))[lane] = acc;
}

// ---------------- GEMMs ----------------
__global__ void k_zero_stats() {
    int c = threadIdx.x;
    g_sum[c] = 0.f;
    g_sumsq[c] = 0.f;
}

// layer 0: [NN,26(pad32)] @ [26,128], fp32 SIMT, BN-stats epilogue
__global__ void k_gemm_l0(const float* __restrict__ W, const float* __restrict__ b) {
    __shared__ float Wsh[INC * HID];
    __shared__ float xs[8 * 32];
    int c = threadIdx.x; // 0..127
    for (int i = c; i < INC * HID; i += HID) Wsh[i] = W[i];
    float bc = b[c];
    float s = 0.f, ss = 0.f;
    int rbase = blockIdx.x * 64;
    for (int rr = 0; rr < 64; rr += 8) {
        int r = rbase + rr;
        if (r >= NN) break;
        __syncthreads();
        if (c < 64) {
            int j = c >> 3, t = c & 7;
            int gr = r + j;
            ((float4*)xs)[c] = (gr < NN) ? ((const float4*)g_agg)[(size_t)gr * 8 + t]
                                         : make_float4(0.f, 0.f, 0.f, 0.f);
        }
        __syncthreads();
        float acc[8] = {0.f,0.f,0.f,0.f,0.f,0.f,0.f,0.f};
#pragma unroll
        for (int k = 0; k < INC; k++) {
            float w = Wsh[k * HID + c];
#pragma unroll
            for (int j = 0; j < 8; j++) acc[j] = fmaf(xs[j * 32 + k], w, acc[j]);
        }
#pragma unroll
        for (int j = 0; j < 8; j++) {
            int gr = r + j;
            if (gr < NN) {
                float y = acc[j] * g_norm_dst[gr] + bc;
                g_x[(size_t)gr * HID + c] = y;
                s += y;
                ss = fmaf(y, y, ss);
            }
        }
    }
    atomicAdd(&g_sum[c], s);
    atomicAdd(&g_sumsq[c], ss);
}

// ---- hidden GEMM: 3xTF32 error-compensated tensor cores, persistent ----
// block: 256 thr (8 warps), tile 64 rows x 128 cols; warp tile 16x64 (8 n-tiles m16n8k8)
// D = Ahi*Bhi + Ahi*Blo + Alo*Bhi  (residual error ~2^-22, effectively fp32)
#define GT_GRID 148
#define GT_LDW 132
#define GT_WHI 0
#define GT_WLO (128 * GT_LDW)
#define GT_XHI (2 * 128 * GT_LDW)
#define GT_XLO (2 * 128 * GT_LDW + 64 * GT_LDW)
#define GT_SMEM ((2 * 128 * GT_LDW + 2 * 64 * GT_LDW) * 4)

__device__ __forceinline__ void tf32_split(float v, unsigned int& hi, unsigned int& lo) {
    asm("cvt.rna.tf32.f32 %0, %1;" : "=r"(hi) : "f"(v));
    float rem = v - __uint_as_float(hi);
    asm("cvt.rna.tf32.f32 %0, %1;" : "=r"(lo) : "f"(rem));
}

__global__ void __launch_bounds__(256, 1) k_gemm_tf32(const float* __restrict__ W,
                                                      const float* __restrict__ b) {
    extern __shared__ float sm[];
    float* Whi = sm + GT_WHI;
    float* Wlo = sm + GT_WLO;
    float* xhi = sm + GT_XHI;
    float* xlo = sm + GT_XLO;
    int tid = threadIdx.x, lane = tid & 31, warp = tid >> 5;
    int g = lane >> 2, tg = lane & 3;

    // stage W split into hi/lo tf32
    for (int i = tid; i < 128 * 32; i += 256) {
        int row = i >> 5, t4 = i & 31;
        float4 v = ((const float4*)W)[i];
        uint4 hi, lo;
        tf32_split(v.x, hi.x, lo.x);
        tf32_split(v.y, hi.y, lo.y);
        tf32_split(v.z, hi.z, lo.z);
        tf32_split(v.w, hi.w, lo.w);
        *(uint4*)(Whi + row * GT_LDW + t4 * 4) = hi;
        *(uint4*)(Wlo + row * GT_LDW + t4 * 4) = lo;
    }

    int wrow = (warp & 3) * 16;
    int wcol = (warp >> 2) * 64;
    float bcx[8], bcy[8];
#pragma unroll
    for (int nt = 0; nt < 8; nt++) {
        int c = wcol + nt * 8 + 2 * tg;
        bcx[nt] = __ldg(&b[c]);
        bcy[nt] = __ldg(&b[c + 1]);
    }
    float scol[16], qcol[16];
#pragma unroll
    for (int t = 0; t < 16; t++) { scol[t] = 0.f; qcol[t] = 0.f; }

    for (int rb = blockIdx.x * 64; rb < NN; rb += GT_GRID * 64) {
        __syncthreads();
        for (int i = tid; i < 64 * 32; i += 256) {
            int row = i >> 5, t4 = i & 31;
            int gr = rb + row;
            float4 v = (gr < NN) ? ((const float4*)g_agg)[(size_t)gr * 32 + t4]
                                 : make_float4(0.f, 0.f, 0.f, 0.f);
            uint4 hi, lo;
            tf32_split(v.x, hi.x, lo.x);
            tf32_split(v.y, hi.y, lo.y);
            tf32_split(v.z, hi.z, lo.z);
            tf32_split(v.w, hi.w, lo.w);
            *(uint4*)(xhi + row * GT_LDW + t4 * 4) = hi;
            *(uint4*)(xlo + row * GT_LDW + t4 * 4) = lo;
        }
        __syncthreads();

        float d[8][4];
#pragma unroll
        for (int nt = 0; nt < 8; nt++) { d[nt][0]=0.f; d[nt][1]=0.f; d[nt][2]=0.f; d[nt][3]=0.f; }

#pragma unroll
        for (int ks = 0; ks < 16; ks++) {
            int k0 = ks * 8;
            unsigned int ah0 = __float_as_uint(xhi[(wrow + g) * GT_LDW + k0 + tg]);
            unsigned int ah1 = __float_as_uint(xhi[(wrow + g + 8) * GT_LDW + k0 + tg]);
            unsigned int ah2 = __float_as_uint(xhi[(wrow + g) * GT_LDW + k0 + tg + 4]);
            unsigned int ah3 = __float_as_uint(xhi[(wrow + g + 8) * GT_LDW + k0 + tg + 4]);
            unsigned int al0 = __float_as_uint(xlo[(wrow + g) * GT_LDW + k0 + tg]);
            unsigned int al1 = __float_as_uint(xlo[(wrow + g + 8) * GT_LDW + k0 + tg]);
            unsigned int al2 = __float_as_uint(xlo[(wrow + g) * GT_LDW + k0 + tg + 4]);
            unsigned int al3 = __float_as_uint(xlo[(wrow + g + 8) * GT_LDW + k0 + tg + 4]);
#pragma unroll
            for (int nt = 0; nt < 8; nt++) {
                int bcol = wcol + nt * 8 + g;
                unsigned int bh0 = __float_as_uint(Whi[(k0 + tg) * GT_LDW + bcol]);
                unsigned int bh1 = __float_as_uint(Whi[(k0 + tg + 4) * GT_LDW + bcol]);
                unsigned int bl0 = __float_as_uint(Wlo[(k0 + tg) * GT_LDW + bcol]);
                unsigned int bl1 = __float_as_uint(Wlo[(k0 + tg + 4) * GT_LDW + bcol]);
#define MMA(A0,A1,A2,A3,B0,B1) \
                asm volatile( \
                    "mma.sync.aligned.m16n8k8.row.col.f32.tf32.tf32.f32 " \
                    "{%0,%1,%2,%3}, {%4,%5,%6,%7}, {%8,%9}, {%0,%1,%2,%3};" \
                    : "+f"(d[nt][0]), "+f"(d[nt][1]), "+f"(d[nt][2]), "+f"(d[nt][3]) \
                    : "r"(A0), "r"(A1), "r"(A2), "r"(A3), "r"(B0), "r"(B1));
                MMA(ah0, ah1, ah2, ah3, bh0, bh1)
                MMA(ah0, ah1, ah2, ah3, bl0, bl1)
                MMA(al0, al1, al2, al3, bh0, bh1)
#undef MMA
            }
        }

        int r0 = rb + wrow + g;
        int r1 = r0 + 8;
        bool v0 = r0 < NN, v1 = r1 < NN;
        float nd0 = v0 ? g_norm_dst[r0] : 0.f;
        float nd1 = v1 ? g_norm_dst[r1] : 0.f;
#pragma unroll
        for (int nt = 0; nt < 8; nt++) {
            int c = wcol + nt * 8 + 2 * tg;
            if (v0) {
                float yx = d[nt][0] * nd0 + bcx[nt];
                float yy = d[nt][1] * nd0 + bcy[nt];
                *(float2*)(g_x + (size_t)r0 * HID + c) = make_float2(yx, yy);
                scol[nt * 2] += yx;     qcol[nt * 2]     = fmaf(yx, yx, qcol[nt * 2]);
                scol[nt * 2 + 1] += yy; qcol[nt * 2 + 1] = fmaf(yy, yy, qcol[nt * 2 + 1]);
            }
            if (v1) {
                float yx = d[nt][2] * nd1 + bcx[nt];
                float yy = d[nt][3] * nd1 + bcy[nt];
                *(float2*)(g_x + (size_t)r1 * HID + c) = make_float2(yx, yy);
                scol[nt * 2] += yx;     qcol[nt * 2]     = fmaf(yx, yx, qcol[nt * 2]);
                scol[nt * 2 + 1] += yy; qcol[nt * 2 + 1] = fmaf(yy, yy, qcol[nt * 2 + 1]);
            }
        }
    }

    // reduce BN stats across the 8 g-lanes sharing each column
#pragma unroll
    for (int t = 0; t < 16; t++) {
        scol[t] += __shfl_xor_sync(0xffffffff, scol[t], 4);
        scol[t] += __shfl_xor_sync(0xffffffff, scol[t], 8);
        scol[t] += __shfl_xor_sync(0xffffffff, scol[t], 16);
        qcol[t] += __shfl_xor_sync(0xffffffff, qcol[t], 4);
        qcol[t] += __shfl_xor_sync(0xffffffff, qcol[t], 8);
        qcol[t] += __shfl_xor_sync(0xffffffff, qcol[t], 16);
    }
    if (g == 0) {
#pragma unroll
        for (int nt = 0; nt < 8; nt++) {
            int c = wcol + nt * 8 + 2 * tg;
            atomicAdd(&g_sum[c],     scol[nt * 2]);
            atomicAdd(&g_sum[c + 1], scol[nt * 2 + 1]);
            atomicAdd(&g_sumsq[c],     qcol[nt * 2]);
            atomicAdd(&g_sumsq[c + 1], qcol[nt * 2 + 1]);
        }
    }
}

__global__ void k_bnfinal(const float* __restrict__ g, const float* __restrict__ bt) {
    int c = threadIdx.x;
    float inv_n = 1.f / (float)NN;
    float mu = g_sum[c] * inv_n;
    float var = g_sumsq[c] * inv_n - mu * mu;
    float sc = g[c] * rsqrtf(var + BN_EPS);
    g_scale[c] = sc;
    g_shift[c] = bt[c] - mu * sc;
}

// final FC: applies BN2 + ReLU on load, then [NN,128]@[128,64]+bfc -> d_out
__global__ void k_fc(const float* __restrict__ W, const float* __restrict__ b,
                     float* __restrict__ out) {
    __shared__ float Wsh[HID * OUTC];
    __shared__ float xs[8 * HID];
    __shared__ float scs[HID], shs[HID];
    int c = threadIdx.x; // 0..63
    for (int i = c; i < HID * OUTC; i += OUTC) Wsh[i] = W[i];
    for (int i = c; i < HID; i += OUTC) { scs[i] = g_scale[i]; shs[i] = g_shift[i]; }
    float bc = b[c];
    int rbase = blockIdx.x * 64;
    for (int rr = 0; rr < 64; rr += 8) {
        int r = rbase + rr;
        if (r >= NN) break;
        __syncthreads();
        for (int i = c; i < 8 * HID; i += OUTC) {
            int j = i >> 7, k = i & 127;
            int gr = r + j;
            float v = (gr < NN) ? g_x[(size_t)gr * HID + k] : 0.f;
            xs[i] = fmaxf(fmaf(v, scs[k], shs[k]), 0.f);
        }
        __syncthreads();
        float acc[8] = {0.f,0.f,0.f,0.f,0.f,0.f,0.f,0.f};
        const float4* xv = (const float4*)xs;
#pragma unroll 4
        for (int k4 = 0; k4 < 32; k4++) {
            float w0 = Wsh[(k4 * 4 + 0) * OUTC + c];
            float w1 = Wsh[(k4 * 4 + 1) * OUTC + c];
            float w2 = Wsh[(k4 * 4 + 2) * OUTC + c];
            float w3 = Wsh[(k4 * 4 + 3) * OUTC + c];
#pragma unroll
            for (int j = 0; j < 8; j++) {
                float4 x4 = xv[j * 32 + k4];
                acc[j] = fmaf(x4.x, w0, acc[j]);
                acc[j] = fmaf(x4.y, w1, acc[j]);
                acc[j] = fmaf(x4.z, w2, acc[j]);
                acc[j] = fmaf(x4.w, w3, acc[j]);
            }
        }
#pragma unroll
        for (int j = 0; j < 8; j++) {
            int gr = r + j;
            if (gr < NN) out[(size_t)gr * OUTC + c] = acc[j] + bc;
        }
    }
}

// ---------------- launch ----------------
extern "C" void kernel_launch(void* const* d_in, const int* in_sizes, int n_in,
                              void* d_out, int out_size) {
    const float* h   = (const float*)d_in[0];
    const int*   src = (const int*)d_in[1];
    const int*   dst = (const int*)d_in[2];
    const float* w0  = (const float*)d_in[3];
    const float* b0  = (const float*)d_in[4];
    const float* w1  = (const float*)d_in[5];
    const float* b1  = (const float*)d_in[6];
    const float* w2  = (const float*)d_in[7];
    const float* b2  = (const float*)d_in[8];
    const float* g0  = (const float*)d_in[9];
    const float* bt0 = (const float*)d_in[10];
    const float* g1  = (const float*)d_in[11];
    const float* bt1 = (const float*)d_in[12];
    const float* g2  = (const float*)d_in[13];
    const float* bt2 = (const float*)d_in[14];
    const float* wfc = (const float*)d_in[15];
    const float* bfc = (const float*)d_in[16];
    float* out = (float*)d_out;

    cudaFuncSetAttribute(k_gemm_tf32, cudaFuncAttributeMaxDynamicSharedMemorySize, GT_SMEM);

    // graph prep: degrees, norms, node weights, fp16 layer-0 messages, CSR
    k_zero_deg<<<(NN + 255) / 256, 256>>>();
    k_degrees<<<(NE + 255) / 256, 256>>>(src, dst);
    k_nodeprep<<<(NN + 255) / 256, 256>>>(h, out);
    k_alloc<<<(NN + 255) / 256, 256>>>();
    k_fill<<<(NE + 255) / 256, 256>>>(src, dst);

    // ---- layer 0 (26 -> 128) ----
    k_gather26<<<(NN * 32 + 255) / 256, 256>>>();
    k_zero_stats<<<1, HID>>>();
    k_gemm_l0<<<(NN + 63) / 64, 128>>>(w0, b0);
    k_bnfinal<<<1, HID>>>(g0, bt0);

    // ---- layers 1, 2 (128 -> 128), 3xTF32 tensor-core GEMM ----
    const float* Ws[2]  = {w1, w2};
    const float* bs[2]  = {b1, b2};
    const float* gs[2]  = {g1, g2};
    const float* bts[2] = {bt1, bt2};
    for (int l = 0; l < 2; l++) {
        k_prescale<<<(NN * (HID / 4) + 255) / 256, 256>>>();
        k_gather128<<<(NN * 32 + 255) / 256, 256>>>();
        k_zero_stats<<<1, HID>>>();
        k_gemm_tf32<<<GT_GRID, 256, GT_SMEM>>>(Ws[l], bs[l]);
        k_bnfinal<<<1, HID>>>(gs[l], bts[l]);
    }

    // ---- final FC (128 -> 64), BN2+ReLU fused into load ----
    k_fc<<<(NN + 63) / 64, 64>>>(wfc, bfc, out);
}

// round 8
// speedup vs baseline: 2.4038x; 1.0951x over previous
#include <cuda_runtime.h>
#include <cuda_fp16.h>

#define NN   100000
#define NE   1600000
#define INC  26
#define HID  128
#define OUTC 64
#define BN_EPS 1e-5f
#define OUT_ELEMS (NN * OUTC)

// ---------------- device scratch ----------------
__device__ float  g_x[NN * HID];    // raw (pre-BN) layer outputs, fp32
__device__ __half g_xh[NN * HID];   // pre-scaled activations, fp16 (gather input)
__device__ __half g_h16[NN * 32];   // layer-0 messages: half(h * norm_src), padded to 32ch
__device__ float  g_agg[NN * HID];  // gather accumulator (layer0 uses NN*32 padded)
__device__ float  g_norm_src[NN];
__device__ float  g_norm_dst[NN];
__device__ int    g_deg_out_i[NN];
__device__ int    g_deg_in_i[NN];
__device__ int    g_rowptr[NN];
__device__ int    g_cursor[NN];
__device__ int    g_csr_src[NE];
__device__ int    g_total;
__device__ float  g_sum[HID];
__device__ float  g_sumsq[HID];
__device__ float  g_scale[HID];
__device__ float  g_shift[HID];

__constant__ float c_wtable[26] = {
    0.7f,0.9f,0.7f,0.9f,0.3f,0.7f,0.3f,0.9f,0.3f,0.3f,0.9f,0.7f,0.1f,
    0.9f,0.5f,0.9f,0.5f,0.5f,0.1f,0.3f,0.7f,0.9f,0.9f,0.9f,0.9f,0.9f};

__device__ __forceinline__ void tf32_split(float v, unsigned int& hi, unsigned int& lo) {
    asm("cvt.rna.tf32.f32 %0, %1;" : "=r"(hi) : "f"(v));
    float rem = v - __uint_as_float(hi);
    asm("cvt.rna.tf32.f32 %0, %1;" : "=r"(lo) : "f"(rem));
}

// ---------------- prep kernels ----------------
__global__ void k_zero_deg() {
    int n = blockIdx.x * blockDim.x + threadIdx.x;
    if (n < NN) { g_deg_out_i[n] = 0; g_deg_in_i[n] = 0; }
    if (n == 0) g_total = 0;
}

__global__ void k_degrees(const int* __restrict__ src, const int* __restrict__ dst) {
    int e = blockIdx.x * blockDim.x + threadIdx.x;
    if (e < NE) {
        atomicAdd(&g_deg_out_i[src[e]], 1);
        atomicAdd(&g_deg_in_i[dst[e]], 1);
    }
}

// argmax weight + degree norms + fp16-packed, norm_src-scaled layer-0 messages
__global__ void k_nodeprep(const float* __restrict__ h, float* __restrict__ out) {
    int n = blockIdx.x * blockDim.x + threadIdx.x;
    if (n >= NN) return;
    const float* hr = h + (size_t)n * INC;
    float hv[INC];
    float best = -1e30f;
    int bi = 0;
#pragma unroll
    for (int c = 0; c < INC; c++) {
        float v = hr[c];
        hv[c] = v;
        if (v > best) { best = v; bi = c; }
    }
    out[OUT_ELEMS + n] = c_wtable[bi];
    float ns = rsqrtf(fmaxf((float)g_deg_out_i[n], 1.f));
    g_norm_src[n] = ns;
    g_norm_dst[n] = rsqrtf(fmaxf((float)g_deg_in_i[n], 1.f));
    unsigned int* dsth = (unsigned int*)g_h16 + (size_t)n * 16;
#pragma unroll
    for (int j = 0; j < 13; j++) {
        __half2 p = __floats2half2_rn(hv[2 * j] * ns, hv[2 * j + 1] * ns);
        dsth[j] = *(unsigned int*)&p;
    }
    dsth[13] = 0; dsth[14] = 0; dsth[15] = 0;
}

// warp-aggregated segment allocator + zero BN stats for layer 0
__global__ void k_alloc() {
    if (blockIdx.x == 0 && threadIdx.x < HID) {
        g_sum[threadIdx.x] = 0.f;
        g_sumsq[threadIdx.x] = 0.f;
    }
    int n = blockIdx.x * blockDim.x + threadIdx.x;
    int lane = threadIdx.x & 31;
    int d = (n < NN) ? g_deg_in_i[n] : 0;
    int incl = d;
#pragma unroll
    for (int o = 1; o < 32; o <<= 1) {
        int t = __shfl_up_sync(0xffffffff, incl, o);
        if (lane >= o) incl += t;
    }
    int wtotal = __shfl_sync(0xffffffff, incl, 31);
    int base = 0;
    if (lane == 0) base = atomicAdd(&g_total, wtotal);
    base = __shfl_sync(0xffffffff, base, 0);
    if (n < NN) {
        int pos = base + incl - d;
        g_rowptr[n] = pos;
        g_cursor[n] = pos;
    }
}

__global__ void k_fill(const int* __restrict__ src, const int* __restrict__ dst) {
    int e = blockIdx.x * blockDim.x + threadIdx.x;
    if (e < NE) {
        int pos = atomicAdd(&g_cursor[dst[e]], 1);
        g_csr_src[pos] = src[e];
    }
}

// ---------------- layer-0 gather: fp16 packed rows, half-warp per edge ----------------
// writes all 16 float2 (cols 26..31 naturally zero from zero-padded g_h16)
__global__ void k_gather26() {
    int gid = blockIdx.x * blockDim.x + threadIdx.x;
    int n = gid >> 5;
    int lane = gid & 31;
    if (n >= NN) return;
    int sub = lane & 15;   // channel pair index (2 ch each)
    int w = lane >> 4;     // which edge of the pair
    int start = g_rowptr[n];
    int cnt = g_deg_in_i[n];
    const int* cs = g_csr_src + start;
    const unsigned int* xh = (const unsigned int*)g_h16;
    float2 acc = make_float2(0.f, 0.f);
    int i = 0;
    for (; i + 4 <= cnt; i += 4) {
        int sA = cs[i + w];
        int sB = cs[i + 2 + w];
        unsigned int pA = __ldg(xh + (size_t)sA * 16 + sub);
        unsigned int pB = __ldg(xh + (size_t)sB * 16 + sub);
        float2 a = __half22float2(*(__half2*)&pA);
        float2 b = __half22float2(*(__half2*)&pB);
        acc.x += a.x + b.x;
        acc.y += a.y + b.y;
    }
    for (; i < cnt; i += 2) {
        int e = i + w;
        if (e < cnt) {
            int s = cs[e];
            unsigned int p = __ldg(xh + (size_t)s * 16 + sub);
            float2 a = __half22float2(*(__half2*)&p);
            acc.x += a.x;
            acc.y += a.y;
        }
    }
    acc.x += __shfl_xor_sync(0xffffffff, acc.x, 16);
    acc.y += __shfl_xor_sync(0xffffffff, acc.y, 16);
    if (w == 0) {
        ((float2*)(g_agg + (size_t)n * 32))[sub] = acc;
    }
}

// pre-scale: g_xh <- half(relu(bn(g_x)) * norm_src[row]); also zeros BN stats
__global__ void k_prescale() {
    if (blockIdx.x == 0 && threadIdx.x < HID) {
        g_sum[threadIdx.x] = 0.f;
        g_sumsq[threadIdx.x] = 0.f;
    }
    int i = blockIdx.x * blockDim.x + threadIdx.x; // over NN*32 float4
    if (i >= NN * (HID / 4)) return;
    int lane = i & 31;
    int row = i >> 5;
    float4 sc = ((const float4*)g_scale)[lane];
    float4 sh = ((const float4*)g_shift)[lane];
    float ns = g_norm_src[row];
    float4 v = ((const float4*)g_x)[i];
    float2 lo = make_float2(fmaxf(fmaf(v.x, sc.x, sh.x), 0.f) * ns,
                            fmaxf(fmaf(v.y, sc.y, sh.y), 0.f) * ns);
    float2 hi = make_float2(fmaxf(fmaf(v.z, sc.z, sh.z), 0.f) * ns,
                            fmaxf(fmaf(v.w, sc.w, sh.w), 0.f) * ns);
    __half2 h0 = __float22half2_rn(lo);
    __half2 h1 = __float22half2_rn(hi);
    uint2 packed;
    packed.x = *(unsigned int*)&h0;
    packed.y = *(unsigned int*)&h1;
    ((uint2*)g_xh)[i] = packed;
}

// pure-sum gather over fp16 pre-scaled activations, fp32 accumulation, MLP=8
__global__ void k_gather128() {
    int gid = blockIdx.x * blockDim.x + threadIdx.x;
    int n = gid >> 5;
    int lane = gid & 31;
    if (n >= NN) return;
    int start = g_rowptr[n];
    int cnt = g_deg_in_i[n];
    float4 acc = make_float4(0.f, 0.f, 0.f, 0.f);
    const uint2* xh = (const uint2*)g_xh;
    const int* cs = g_csr_src + start;
    int i = 0;
    for (; i + 8 <= cnt; i += 8) {
        int s0 = cs[i + 0], s1 = cs[i + 1], s2 = cs[i + 2], s3 = cs[i + 3];
        int s4 = cs[i + 4], s5 = cs[i + 5], s6 = cs[i + 6], s7 = cs[i + 7];
        uint2 p0 = __ldg(xh + (size_t)s0 * 32 + lane);
        uint2 p1 = __ldg(xh + (size_t)s1 * 32 + lane);
        uint2 p2 = __ldg(xh + (size_t)s2 * 32 + lane);
        uint2 p3 = __ldg(xh + (size_t)s3 * 32 + lane);
        uint2 p4 = __ldg(xh + (size_t)s4 * 32 + lane);
        uint2 p5 = __ldg(xh + (size_t)s5 * 32 + lane);
        uint2 p6 = __ldg(xh + (size_t)s6 * 32 + lane);
        uint2 p7 = __ldg(xh + (size_t)s7 * 32 + lane);
        float2 a, bb;
#define ACC(P) \
        a = __half22float2(*(__half2*)&P.x); bb = __half22float2(*(__half2*)&P.y); \
        acc.x += a.x; acc.y += a.y; acc.z += bb.x; acc.w += bb.y;
        ACC(p0) ACC(p1) ACC(p2) ACC(p3) ACC(p4) ACC(p5) ACC(p6) ACC(p7)
    }
    for (; i + 2 <= cnt; i += 2) {
        int s0 = cs[i], s1 = cs[i + 1];
        uint2 p0 = __ldg(xh + (size_t)s0 * 32 + lane);
        uint2 p1 = __ldg(xh + (size_t)s1 * 32 + lane);
        float2 a, bb;
        ACC(p0) ACC(p1)
    }
    if (i < cnt) {
        int s0 = cs[i];
        uint2 p0 = __ldg(xh + (size_t)s0 * 32 + lane);
        float2 a, bb;
        ACC(p0)
    }
#undef ACC
    ((float4*)(g_agg + (size_t)n * HID))[lane] = acc;
}

// ---- layer-0 GEMM: 3xTF32, A [NN,32] (zero-padded K), W [26->32,128] ----
#define L0_LDW 132
#define L0_WHI 0
#define L0_WLO (32 * L0_LDW)
#define L0_XHI (2 * 32 * L0_LDW)
#define L0_XLO (2 * 32 * L0_LDW + 64 * L0_LDW)
#define L0_SMEM ((2 * 32 * L0_LDW + 2 * 64 * L0_LDW) * 4)
#define L0_GRID 148
__global__ void __launch_bounds__(256, 1) k_gemm_l0_tf32(const float* __restrict__ W,
                                                         const float* __restrict__ b) {
    extern __shared__ float sm[];
    float* Whi = sm + L0_WHI;
    float* Wlo = sm + L0_WLO;
    float* xhi = sm + L0_XHI;
    float* xlo = sm + L0_XLO;
    int tid = threadIdx.x, lane = tid & 31, warp = tid >> 5;
    int g = lane >> 2, tg = lane & 3;

    // stage W rows 0..25 (zeros for 26..31)
    for (int i = tid; i < 32 * 32; i += 256) {
        int row = i >> 5, t4 = i & 31;
        float4 v = (row < INC) ? ((const float4*)W)[row * 32 + t4]
                               : make_float4(0.f, 0.f, 0.f, 0.f);
        uint4 hi, lo;
        tf32_split(v.x, hi.x, lo.x);
        tf32_split(v.y, hi.y, lo.y);
        tf32_split(v.z, hi.z, lo.z);
        tf32_split(v.w, hi.w, lo.w);
        *(uint4*)(Whi + row * L0_LDW + t4 * 4) = hi;
        *(uint4*)(Wlo + row * L0_LDW + t4 * 4) = lo;
    }

    int wrow = (warp & 3) * 16;
    int wcol = (warp >> 2) * 64;
    float bcx[8], bcy[8];
#pragma unroll
    for (int nt = 0; nt < 8; nt++) {
        int c = wcol + nt * 8 + 2 * tg;
        bcx[nt] = __ldg(&b[c]);
        bcy[nt] = __ldg(&b[c + 1]);
    }
    float scol[16], qcol[16];
#pragma unroll
    for (int t = 0; t < 16; t++) { scol[t] = 0.f; qcol[t] = 0.f; }

    for (int rb = blockIdx.x * 64; rb < NN; rb += L0_GRID * 64) {
        __syncthreads();
        for (int i = tid; i < 64 * 8; i += 256) {
            int row = i >> 3, t4 = i & 7;
            int gr = rb + row;
            float4 v = (gr < NN) ? ((const float4*)g_agg)[(size_t)gr * 8 + t4]
                                 : make_float4(0.f, 0.f, 0.f, 0.f);
            uint4 hi, lo;
            tf32_split(v.x, hi.x, lo.x);
            tf32_split(v.y, hi.y, lo.y);
            tf32_split(v.z, hi.z, lo.z);
            tf32_split(v.w, hi.w, lo.w);
            *(uint4*)(xhi + row * L0_LDW + t4 * 4) = hi;
            *(uint4*)(xlo + row * L0_LDW + t4 * 4) = lo;
        }
        __syncthreads();

        float d[8][4];
#pragma unroll
        for (int nt = 0; nt < 8; nt++) { d[nt][0]=0.f; d[nt][1]=0.f; d[nt][2]=0.f; d[nt][3]=0.f; }

#pragma unroll
        for (int ks = 0; ks < 4; ks++) {
            int k0 = ks * 8;
            unsigned int ah0 = __float_as_uint(xhi[(wrow + g) * L0_LDW + k0 + tg]);
            unsigned int ah1 = __float_as_uint(xhi[(wrow + g + 8) * L0_LDW + k0 + tg]);
            unsigned int ah2 = __float_as_uint(xhi[(wrow + g) * L0_LDW + k0 + tg + 4]);
            unsigned int ah3 = __float_as_uint(xhi[(wrow + g + 8) * L0_LDW + k0 + tg + 4]);
            unsigned int al0 = __float_as_uint(xlo[(wrow + g) * L0_LDW + k0 + tg]);
            unsigned int al1 = __float_as_uint(xlo[(wrow + g + 8) * L0_LDW + k0 + tg]);
            unsigned int al2 = __float_as_uint(xlo[(wrow + g) * L0_LDW + k0 + tg + 4]);
            unsigned int al3 = __float_as_uint(xlo[(wrow + g + 8) * L0_LDW + k0 + tg + 4]);
#pragma unroll
            for (int nt = 0; nt < 8; nt++) {
                int bcol = wcol + nt * 8 + g;
                unsigned int bh0 = __float_as_uint(Whi[(k0 + tg) * L0_LDW + bcol]);
                unsigned int bh1 = __float_as_uint(Whi[(k0 + tg + 4) * L0_LDW + bcol]);
                unsigned int bl0 = __float_as_uint(Wlo[(k0 + tg) * L0_LDW + bcol]);
                unsigned int bl1 = __float_as_uint(Wlo[(k0 + tg + 4) * L0_LDW + bcol]);
#define MMA(A0,A1,A2,A3,B0,B1) \
                asm volatile( \
                    "mma.sync.aligned.m16n8k8.row.col.f32.tf32.tf32.f32 " \
                    "{%0,%1,%2,%3}, {%4,%5,%6,%7}, {%8,%9}, {%0,%1,%2,%3};" \
                    : "+f"(d[nt][0]), "+f"(d[nt][1]), "+f"(d[nt][2]), "+f"(d[nt][3]) \
                    : "r"(A0), "r"(A1), "r"(A2), "r"(A3), "r"(B0), "r"(B1));
                MMA(ah0, ah1, ah2, ah3, bh0, bh1)
                MMA(ah0, ah1, ah2, ah3, bl0, bl1)
                MMA(al0, al1, al2, al3, bh0, bh1)
#undef MMA
            }
        }

        int r0 = rb + wrow + g;
        int r1 = r0 + 8;
        bool v0 = r0 < NN, v1 = r1 < NN;
        float nd0 = v0 ? g_norm_dst[r0] : 0.f;
        float nd1 = v1 ? g_norm_dst[r1] : 0.f;
#pragma unroll
        for (int nt = 0; nt < 8; nt++) {
            int c = wcol + nt * 8 + 2 * tg;
            if (v0) {
                float yx = d[nt][0] * nd0 + bcx[nt];
                float yy = d[nt][1] * nd0 + bcy[nt];
                *(float2*)(g_x + (size_t)r0 * HID + c) = make_float2(yx, yy);
                scol[nt * 2] += yx;     qcol[nt * 2]     = fmaf(yx, yx, qcol[nt * 2]);
                scol[nt * 2 + 1] += yy; qcol[nt * 2 + 1] = fmaf(yy, yy, qcol[nt * 2 + 1]);
            }
            if (v1) {
                float yx = d[nt][2] * nd1 + bcx[nt];
                float yy = d[nt][3] * nd1 + bcy[nt];
                *(float2*)(g_x + (size_t)r1 * HID + c) = make_float2(yx, yy);
                scol[nt * 2] += yx;     qcol[nt * 2]     = fmaf(yx, yx, qcol[nt * 2]);
                scol[nt * 2 + 1] += yy; qcol[nt * 2 + 1] = fmaf(yy, yy, qcol[nt * 2 + 1]);
            }
        }
    }

#pragma unroll
    for (int t = 0; t < 16; t++) {
        scol[t] += __shfl_xor_sync(0xffffffff, scol[t], 4);
        scol[t] += __shfl_xor_sync(0xffffffff, scol[t], 8);
        scol[t] += __shfl_xor_sync(0xffffffff, scol[t], 16);
        qcol[t] += __shfl_xor_sync(0xffffffff, qcol[t], 4);
        qcol[t] += __shfl_xor_sync(0xffffffff, qcol[t], 8);
        qcol[t] += __shfl_xor_sync(0xffffffff, qcol[t], 16);
    }
    if (g == 0) {
#pragma unroll
        for (int nt = 0; nt < 8; nt++) {
            int c = wcol + nt * 8 + 2 * tg;
            atomicAdd(&g_sum[c],     scol[nt * 2]);
            atomicAdd(&g_sum[c + 1], scol[nt * 2 + 1]);
            atomicAdd(&g_sumsq[c],     qcol[nt * 2]);
            atomicAdd(&g_sumsq[c + 1], qcol[nt * 2 + 1]);
        }
    }
}

// ---- hidden GEMM: 3xTF32 error-compensated tensor cores, persistent ----
#define GT_GRID 148
#define GT_LDW 132
#define GT_WHI 0
#define GT_WLO (128 * GT_LDW)
#define GT_XHI (2 * 128 * GT_LDW)
#define GT_XLO (2 * 128 * GT_LDW + 64 * GT_LDW)
#define GT_SMEM ((2 * 128 * GT_LDW + 2 * 64 * GT_LDW) * 4)
__global__ void __launch_bounds__(256, 1) k_gemm_tf32(const float* __restrict__ W,
                                                      const float* __restrict__ b) {
    extern __shared__ float sm[];
    float* Whi = sm + GT_WHI;
    float* Wlo = sm + GT_WLO;
    float* xhi = sm + GT_XHI;
    float* xlo = sm + GT_XLO;
    int tid = threadIdx.x, lane = tid & 31, warp = tid >> 5;
    int g = lane >> 2, tg = lane & 3;

    for (int i = tid; i < 128 * 32; i += 256) {
        int row = i >> 5, t4 = i & 31;
        float4 v = ((const float4*)W)[i];
        uint4 hi, lo;
        tf32_split(v.x, hi.x, lo.x);
        tf32_split(v.y, hi.y, lo.y);
        tf32_split(v.z, hi.z, lo.z);
        tf32_split(v.w, hi.w, lo.w);
        *(uint4*)(Whi + row * GT_LDW + t4 * 4) = hi;
        *(uint4*)(Wlo + row * GT_LDW + t4 * 4) = lo;
    }

    int wrow = (warp & 3) * 16;
    int wcol = (warp >> 2) * 64;
    float bcx[8], bcy[8];
#pragma unroll
    for (int nt = 0; nt < 8; nt++) {
        int c = wcol + nt * 8 + 2 * tg;
        bcx[nt] = __ldg(&b[c]);
        bcy[nt] = __ldg(&b[c + 1]);
    }
    float scol[16], qcol[16];
#pragma unroll
    for (int t = 0; t < 16; t++) { scol[t] = 0.f; qcol[t] = 0.f; }

    for (int rb = blockIdx.x * 64; rb < NN; rb += GT_GRID * 64) {
        __syncthreads();
        for (int i = tid; i < 64 * 32; i += 256) {
            int row = i >> 5, t4 = i & 31;
            int gr = rb + row;
            float4 v = (gr < NN) ? ((const float4*)g_agg)[(size_t)gr * 32 + t4]
                                 : make_float4(0.f, 0.f, 0.f, 0.f);
            uint4 hi, lo;
            tf32_split(v.x, hi.x, lo.x);
            tf32_split(v.y, hi.y, lo.y);
            tf32_split(v.z, hi.z, lo.z);
            tf32_split(v.w, hi.w, lo.w);
            *(uint4*)(xhi + row * GT_LDW + t4 * 4) = hi;
            *(uint4*)(xlo + row * GT_LDW + t4 * 4) = lo;
        }
        __syncthreads();

        float d[8][4];
#pragma unroll
        for (int nt = 0; nt < 8; nt++) { d[nt][0]=0.f; d[nt][1]=0.f; d[nt][2]=0.f; d[nt][3]=0.f; }

#pragma unroll
        for (int ks = 0; ks < 16; ks++) {
            int k0 = ks * 8;
            unsigned int ah0 = __float_as_uint(xhi[(wrow + g) * GT_LDW + k0 + tg]);
            unsigned int ah1 = __float_as_uint(xhi[(wrow + g + 8) * GT_LDW + k0 + tg]);
            unsigned int ah2 = __float_as_uint(xhi[(wrow + g) * GT_LDW + k0 + tg + 4]);
            unsigned int ah3 = __float_as_uint(xhi[(wrow + g + 8) * GT_LDW + k0 + tg + 4]);
            unsigned int al0 = __float_as_uint(xlo[(wrow + g) * GT_LDW + k0 + tg]);
            unsigned int al1 = __float_as_uint(xlo[(wrow + g + 8) * GT_LDW + k0 + tg]);
            unsigned int al2 = __float_as_uint(xlo[(wrow + g) * GT_LDW + k0 + tg + 4]);
            unsigned int al3 = __float_as_uint(xlo[(wrow + g + 8) * GT_LDW + k0 + tg + 4]);
#pragma unroll
            for (int nt = 0; nt < 8; nt++) {
                int bcol = wcol + nt * 8 + g;
                unsigned int bh0 = __float_as_uint(Whi[(k0 + tg) * GT_LDW + bcol]);
                unsigned int bh1 = __float_as_uint(Whi[(k0 + tg + 4) * GT_LDW + bcol]);
                unsigned int bl0 = __float_as_uint(Wlo[(k0 + tg) * GT_LDW + bcol]);
                unsigned int bl1 = __float_as_uint(Wlo[(k0 + tg + 4) * GT_LDW + bcol]);
#define MMA(A0,A1,A2,A3,B0,B1) \
                asm volatile( \
                    "mma.sync.aligned.m16n8k8.row.col.f32.tf32.tf32.f32 " \
                    "{%0,%1,%2,%3}, {%4,%5,%6,%7}, {%8,%9}, {%0,%1,%2,%3};" \
                    : "+f"(d[nt][0]), "+f"(d[nt][1]), "+f"(d[nt][2]), "+f"(d[nt][3]) \
                    : "r"(A0), "r"(A1), "r"(A2), "r"(A3), "r"(B0), "r"(B1));
                MMA(ah0, ah1, ah2, ah3, bh0, bh1)
                MMA(ah0, ah1, ah2, ah3, bl0, bl1)
                MMA(al0, al1, al2, al3, bh0, bh1)
#undef MMA
            }
        }

        int r0 = rb + wrow + g;
        int r1 = r0 + 8;
        bool v0 = r0 < NN, v1 = r1 < NN;
        float nd0 = v0 ? g_norm_dst[r0] : 0.f;
        float nd1 = v1 ? g_norm_dst[r1] : 0.f;
#pragma unroll
        for (int nt = 0; nt < 8; nt++) {
            int c = wcol + nt * 8 + 2 * tg;
            if (v0) {
                float yx = d[nt][0] * nd0 + bcx[nt];
                float yy = d[nt][1] * nd0 + bcy[nt];
                *(float2*)(g_x + (size_t)r0 * HID + c) = make_float2(yx, yy);
                scol[nt * 2] += yx;     qcol[nt * 2]     = fmaf(yx, yx, qcol[nt * 2]);
                scol[nt * 2 + 1] += yy; qcol[nt * 2 + 1] = fmaf(yy, yy, qcol[nt * 2 + 1]);
            }
            if (v1) {
                float yx = d[nt][2] * nd1 + bcx[nt];
                float yy = d[nt][3] * nd1 + bcy[nt];
                *(float2*)(g_x + (size_t)r1 * HID + c) = make_float2(yx, yy);
                scol[nt * 2] += yx;     qcol[nt * 2]     = fmaf(yx, yx, qcol[nt * 2]);
                scol[nt * 2 + 1] += yy; qcol[nt * 2 + 1] = fmaf(yy, yy, qcol[nt * 2 + 1]);
            }
        }
    }

#pragma unroll
    for (int t = 0; t < 16; t++) {
        scol[t] += __shfl_xor_sync(0xffffffff, scol[t], 4);
        scol[t] += __shfl_xor_sync(0xffffffff, scol[t], 8);
        scol[t] += __shfl_xor_sync(0xffffffff, scol[t], 16);
        qcol[t] += __shfl_xor_sync(0xffffffff, qcol[t], 4);
        qcol[t] += __shfl_xor_sync(0xffffffff, qcol[t], 8);
        qcol[t] += __shfl_xor_sync(0xffffffff, qcol[t], 16);
    }
    if (g == 0) {
#pragma unroll
        for (int nt = 0; nt < 8; nt++) {
            int c = wcol + nt * 8 + 2 * tg;
            atomicAdd(&g_sum[c],     scol[nt * 2]);
            atomicAdd(&g_sum[c + 1], scol[nt * 2 + 1]);
            atomicAdd(&g_sumsq[c],     qcol[nt * 2]);
            atomicAdd(&g_sumsq[c + 1], qcol[nt * 2 + 1]);
        }
    }
}

__global__ void k_bnfinal(const float* __restrict__ g, const float* __restrict__ bt) {
    int c = threadIdx.x;
    float inv_n = 1.f / (float)NN;
    float mu = g_sum[c] * inv_n;
    float var = g_sumsq[c] * inv_n - mu * mu;
    float sc = g[c] * rsqrtf(var + BN_EPS);
    g_scale[c] = sc;
    g_shift[c] = bt[c] - mu * sc;
}

// ---- final FC: 3xTF32 tensor cores; BN2+ReLU applied during fp32 staging ----
// block 256 (8 warps), tile 64 rows x 64 cols; warp tile 16x32 (4 n-tiles)
#define FC_GRID 148
#define FC_LDWW 68
#define FC_LDX 132
#define FC_WHI 0
#define FC_WLO (128 * FC_LDWW)
#define FC_XHI (2 * 128 * FC_LDWW)
#define FC_XLO (2 * 128 * FC_LDWW + 64 * FC_LDX)
#define FC_SC  (2 * 128 * FC_LDWW + 2 * 64 * FC_LDX)
#define FC_SMEM ((2 * 128 * FC_LDWW + 2 * 64 * FC_LDX + 2 * HID) * 4)
__global__ void __launch_bounds__(256, 1) k_fc_tf32(const float* __restrict__ W,
                                                    const float* __restrict__ b,
                                                    float* __restrict__ out) {
    extern __shared__ float sm[];
    float* Whi = sm + FC_WHI;
    float* Wlo = sm + FC_WLO;
    float* xhi = sm + FC_XHI;
    float* xlo = sm + FC_XLO;
    float* scs = sm + FC_SC;
    float* shs = scs + HID;
    int tid = threadIdx.x, lane = tid & 31, warp = tid >> 5;
    int g = lane >> 2, tg = lane & 3;

    if (tid < HID) { scs[tid] = g_scale[tid]; shs[tid] = g_shift[tid]; }
    // stage Wfc [128][64] hi/lo
    for (int i = tid; i < 128 * 16; i += 256) {
        int row = i >> 4, t4 = i & 15;
        float4 v = ((const float4*)W)[i];
        uint4 hi, lo;
        tf32_split(v.x, hi.x, lo.x);
        tf32_split(v.y, hi.y, lo.y);
        tf32_split(v.z, hi.z, lo.z);
        tf32_split(v.w, hi.w, lo.w);
        *(uint4*)(Whi + row * FC_LDWW + t4 * 4) = hi;
        *(uint4*)(Wlo + row * FC_LDWW + t4 * 4) = lo;
    }

    int wrow = (warp & 3) * 16;
    int wcol = (warp >> 2) * 32;
    float bcx[4], bcy[4];
#pragma unroll
    for (int nt = 0; nt < 4; nt++) {
        int c = wcol + nt * 8 + 2 * tg;
        bcx[nt] = __ldg(&b[c]);
        bcy[nt] = __ldg(&b[c + 1]);
    }
    __syncthreads();

    for (int rb = blockIdx.x * 64; rb < NN; rb += FC_GRID * 64) {
        __syncthreads();
        for (int i = tid; i < 64 * 32; i += 256) {
            int row = i >> 5, t4 = i & 31;
            int gr = rb + row;
            float4 v = (gr < NN) ? ((const float4*)g_x)[(size_t)gr * 32 + t4]
                                 : make_float4(0.f, 0.f, 0.f, 0.f);
            int k = t4 * 4;
            v.x = fmaxf(fmaf(v.x, scs[k + 0], shs[k + 0]), 0.f);
            v.y = fmaxf(fmaf(v.y, scs[k + 1], shs[k + 1]), 0.f);
            v.z = fmaxf(fmaf(v.z, scs[k + 2], shs[k + 2]), 0.f);
            v.w = fmaxf(fmaf(v.w, scs[k + 3], shs[k + 3]), 0.f);
            uint4 hi, lo;
            tf32_split(v.x, hi.x, lo.x);
            tf32_split(v.y, hi.y, lo.y);
            tf32_split(v.z, hi.z, lo.z);
            tf32_split(v.w, hi.w, lo.w);
            *(uint4*)(xhi + row * FC_LDX + t4 * 4) = hi;
            *(uint4*)(xlo + row * FC_LDX + t4 * 4) = lo;
        }
        __syncthreads();

        float d[4][4];
#pragma unroll
        for (int nt = 0; nt < 4; nt++) { d[nt][0]=0.f; d[nt][1]=0.f; d[nt][2]=0.f; d[nt][3]=0.f; }

#pragma unroll
        for (int ks = 0; ks < 16; ks++) {
            int k0 = ks * 8;
            unsigned int ah0 = __float_as_uint(xhi[(wrow + g) * FC_LDX + k0 + tg]);
            unsigned int ah1 = __float_as_uint(xhi[(wrow + g + 8) * FC_LDX + k0 + tg]);
            unsigned int ah2 = __float_as_uint(xhi[(wrow + g) * FC_LDX + k0 + tg + 4]);
            unsigned int ah3 = __float_as_uint(xhi[(wrow + g + 8) * FC_LDX + k0 + tg + 4]);
            unsigned int al0 = __float_as_uint(xlo[(wrow + g) * FC_LDX + k0 + tg]);
            unsigned int al1 = __float_as_uint(xlo[(wrow + g + 8) * FC_LDX + k0 + tg]);
            unsigned int al2 = __float_as_uint(xlo[(wrow + g) * FC_LDX + k0 + tg + 4]);
            unsigned int al3 = __float_as_uint(xlo[(wrow + g + 8) * FC_LDX + k0 + tg + 4]);
#pragma unroll
            for (int nt = 0; nt < 4; nt++) {
                int bcol = wcol + nt * 8 + g;
                unsigned int bh0 = __float_as_uint(Whi[(k0 + tg) * FC_LDWW + bcol]);
                unsigned int bh1 = __float_as_uint(Whi[(k0 + tg + 4) * FC_LDWW + bcol]);
                unsigned int bl0 = __float_as_uint(Wlo[(k0 + tg) * FC_LDWW + bcol]);
                unsigned int bl1 = __float_as_uint(Wlo[(k0 + tg + 4) * FC_LDWW + bcol]);
#define MMA(A0,A1,A2,A3,B0,B1) \
                asm volatile( \
                    "mma.sync.aligned.m16n8k8.row.col.f32.tf32.tf32.f32 " \
                    "{%0,%1,%2,%3}, {%4,%5,%6,%7}, {%8,%9}, {%0,%1,%2,%3};" \
                    : "+f"(d[nt][0]), "+f"(d[nt][1]), "+f"(d[nt][2]), "+f"(d[nt][3]) \
                    : "r"(A0), "r"(A1), "r"(A2), "r"(A3), "r"(B0), "r"(B1));
                MMA(ah0, ah1, ah2, ah3, bh0, bh1)
                MMA(ah0, ah1, ah2, ah3, bl0, bl1)
                MMA(al0, al1, al2, al3, bh0, bh1)
#undef MMA
            }
        }

        int r0 = rb + wrow + g;
        int r1 = r0 + 8;
#pragma unroll
        for (int nt = 0; nt < 4; nt++) {
            int c = wcol + nt * 8 + 2 * tg;
            if (r0 < NN)
                *(float2*)(out + (size_t)r0 * OUTC + c) =
                    make_float2(d[nt][0] + bcx[nt], d[nt][1] + bcy[nt]);
            if (r1 < NN)
                *(float2*)(out + (size_t)r1 * OUTC + c) =
                    make_float2(d[nt][2] + bcx[nt], d[nt][3] + bcy[nt]);
        }
    }
}

// ---------------- launch ----------------
extern "C" void kernel_launch(void* const* d_in, const int* in_sizes, int n_in,
                              void* d_out, int out_size) {
    const float* h   = (const float*)d_in[0];
    const int*   src = (const int*)d_in[1];
    const int*   dst = (const int*)d_in[2];
    const float* w0  = (const float*)d_in[3];
    const float* b0  = (const float*)d_in[4];
    const float* w1  = (const float*)d_in[5];
    const float* b1  = (const float*)d_in[6];
    const float* w2  = (const float*)d_in[7];
    const float* b2  = (const float*)d_in[8];
    const float* g0  = (const float*)d_in[9];
    const float* bt0 = (const float*)d_in[10];
    const float* g1  = (const float*)d_in[11];
    const float* bt1 = (const float*)d_in[12];
    const float* g2  = (const float*)d_in[13];
    const float* bt2 = (const float*)d_in[14];
    const float* wfc = (const float*)d_in[15];
    const float* bfc = (const float*)d_in[16];
    float* out = (float*)d_out;

    cudaFuncSetAttribute(k_gemm_tf32, cudaFuncAttributeMaxDynamicSharedMemorySize, GT_SMEM);
    cudaFuncSetAttribute(k_gemm_l0_tf32, cudaFuncAttributeMaxDynamicSharedMemorySize, L0_SMEM);
    cudaFuncSetAttribute(k_fc_tf32, cudaFuncAttributeMaxDynamicSharedMemorySize, FC_SMEM);

    // graph prep: degrees, norms, node weights, fp16 layer-0 messages, CSR
    k_zero_deg<<<(NN + 255) / 256, 256>>>();
    k_degrees<<<(NE + 255) / 256, 256>>>(src, dst);
    k_nodeprep<<<(NN + 255) / 256, 256>>>(h, out);
    k_alloc<<<(NN + 255) / 256, 256>>>();   // also zeros layer-0 BN stats
    k_fill<<<(NE + 255) / 256, 256>>>(src, dst);

    // ---- layer 0 (26 -> 128), 3xTF32 ----
    k_gather26<<<(NN * 32 + 255) / 256, 256>>>();
    k_gemm_l0_tf32<<<L0_GRID, 256, L0_SMEM>>>(w0, b0);
    k_bnfinal<<<1, HID>>>(g0, bt0);

    // ---- layers 1, 2 (128 -> 128), 3xTF32 ----
    const float* Ws[2]  = {w1, w2};
    const float* bs[2]  = {b1, b2};
    const float* gs[2]  = {g1, g2};
    const float* bts[2] = {bt1, bt2};
    for (int l = 0; l < 2; l++) {
        k_prescale<<<(NN * (HID / 4) + 255) / 256, 256>>>();  // also zeros BN stats
        k_gather128<<<(NN * 32 + 255) / 256, 256>>>();
        k_gemm_tf32<<<GT_GRID, 256, GT_SMEM>>>(Ws[l], bs[l]);
        k_bnfinal<<<1, HID>>>(gs[l], bts[l]);
    }

    // ---- final FC (128 -> 64), 3xTF32, BN2+ReLU fused into staging ----
    k_fc_tf32<<<FC_GRID, 256, FC_SMEM>>>(wfc, bfc, out);
}

// round 9
// speedup vs baseline: 2.4673x; 1.0264x over previous
#include <cuda_runtime.h>
#include <cuda_fp16.h>

#define NN   100000
#define NE   1600000
#define INC  26
#define HID  128
#define OUTC 64
#define BN_EPS 1e-5f
#define OUT_ELEMS (NN * OUTC)
#define CSR_CAP (NE + 4 * NN)

// ---------------- device scratch ----------------
__device__ float  g_x[NN * HID];    // raw (pre-BN) layer outputs, fp32
__device__ __half g_xh[NN * HID];   // pre-scaled activations, fp16 (gather input)
__device__ __half g_h16[NN * 32];   // layer-0 messages: half(h * norm_src), padded to 32ch
__device__ float  g_agg[NN * HID];  // gather accumulator (layer0 uses NN*32 padded)
__device__ float  g_norm_src[NN];
__device__ float  g_norm_dst[NN];
__device__ int    g_deg_out_i[NN];
__device__ int    g_deg_in_i[NN];
__device__ int    g_rowptr[NN];
__device__ int    g_cursor[NN];
__device__ int    g_csr_src[CSR_CAP];
__device__ int    g_total;
__device__ float  g_sum[3 * HID];   // BN stats, one slot per BN layer
__device__ float  g_sumsq[3 * HID];

__constant__ float c_wtable[26] = {
    0.7f,0.9f,0.7f,0.9f,0.3f,0.7f,0.3f,0.9f,0.3f,0.3f,0.9f,0.7f,0.1f,
    0.9f,0.5f,0.9f,0.5f,0.5f,0.1f,0.3f,0.7f,0.9f,0.9f,0.9f,0.9f,0.9f};

__device__ __forceinline__ void tf32_split(float v, unsigned int& hi, unsigned int& lo) {
    asm("cvt.rna.tf32.f32 %0, %1;" : "=r"(hi) : "f"(v));
    float rem = v - __uint_as_float(hi);
    asm("cvt.rna.tf32.f32 %0, %1;" : "=r"(lo) : "f"(rem));
}

// ---------------- prep kernels ----------------
__global__ void k_zero_deg() {
    int n = blockIdx.x * blockDim.x + threadIdx.x;
    if (n < NN) { g_deg_out_i[n] = 0; g_deg_in_i[n] = 0; }
    if (n < 3 * HID) { g_sum[n] = 0.f; g_sumsq[n] = 0.f; }
    if (n == 0) g_total = 0;
}

__global__ void k_degrees(const int* __restrict__ src, const int* __restrict__ dst) {
    int e = blockIdx.x * blockDim.x + threadIdx.x;
    if (e < NE) {
        atomicAdd(&g_deg_out_i[src[e]], 1);
        atomicAdd(&g_deg_in_i[dst[e]], 1);
    }
}

// argmax weight + degree norms + fp16-packed, norm_src-scaled layer-0 messages
__global__ void k_nodeprep(const float* __restrict__ h, float* __restrict__ out) {
    int n = blockIdx.x * blockDim.x + threadIdx.x;
    if (n >= NN) return;
    const float* hr = h + (size_t)n * INC;
    float hv[INC];
    float best = -1e30f;
    int bi = 0;
#pragma unroll
    for (int c = 0; c < INC; c++) {
        float v = hr[c];
        hv[c] = v;
        if (v > best) { best = v; bi = c; }
    }
    out[OUT_ELEMS + n] = c_wtable[bi];
    float ns = rsqrtf(fmaxf((float)g_deg_out_i[n], 1.f));
    g_norm_src[n] = ns;
    g_norm_dst[n] = rsqrtf(fmaxf((float)g_deg_in_i[n], 1.f));
    unsigned int* dsth = (unsigned int*)g_h16 + (size_t)n * 16;
#pragma unroll
    for (int j = 0; j < 13; j++) {
        __half2 p = __floats2half2_rn(hv[2 * j] * ns, hv[2 * j + 1] * ns);
        dsth[j] = *(unsigned int*)&p;
    }
    dsth[13] = 0; dsth[14] = 0; dsth[15] = 0;
}

// warp-aggregated segment allocator; segments padded to multiple of 4 ints
// so csr index loads can be int4-vectorized
__global__ void k_alloc() {
    int n = blockIdx.x * blockDim.x + threadIdx.x;
    int lane = threadIdx.x & 31;
    int d = (n < NN) ? ((g_deg_in_i[n] + 3) & ~3) : 0;
    int incl = d;
#pragma unroll
    for (int o = 1; o < 32; o <<= 1) {
        int t = __shfl_up_sync(0xffffffff, incl, o);
        if (lane >= o) incl += t;
    }
    int wtotal = __shfl_sync(0xffffffff, incl, 31);
    int base = 0;
    if (lane == 0) base = atomicAdd(&g_total, wtotal);
    base = __shfl_sync(0xffffffff, base, 0);
    if (n < NN) {
        int pos = base + incl - d;
        g_rowptr[n] = pos;
        g_cursor[n] = pos;
    }
}

__global__ void k_fill(const int* __restrict__ src, const int* __restrict__ dst) {
    int e = blockIdx.x * blockDim.x + threadIdx.x;
    if (e < NE) {
        int pos = atomicAdd(&g_cursor[dst[e]], 1);
        g_csr_src[pos] = src[e];
    }
}

// ---------------- layer-0 gather: fp16 packed rows, half-warp per edge ----------------
__global__ void k_gather26() {
    int gid = blockIdx.x * blockDim.x + threadIdx.x;
    int n = gid >> 5;
    int lane = gid & 31;
    if (n >= NN) return;
    int sub = lane & 15;
    int w = lane >> 4;
    int start = g_rowptr[n];
    int cnt = g_deg_in_i[n];
    const int* cs = g_csr_src + start;
    const unsigned int* xh = (const unsigned int*)g_h16;
    float2 acc = make_float2(0.f, 0.f);
    int i = 0;
    for (; i + 4 <= cnt; i += 4) {
        int sA = cs[i + w];
        int sB = cs[i + 2 + w];
        unsigned int pA = __ldg(xh + (size_t)sA * 16 + sub);
        unsigned int pB = __ldg(xh + (size_t)sB * 16 + sub);
        float2 a = __half22float2(*(__half2*)&pA);
        float2 b = __half22float2(*(__half2*)&pB);
        acc.x += a.x + b.x;
        acc.y += a.y + b.y;
    }
    for (; i < cnt; i += 2) {
        int e = i + w;
        if (e < cnt) {
            int s = cs[e];
            unsigned int p = __ldg(xh + (size_t)s * 16 + sub);
            float2 a = __half22float2(*(__half2*)&p);
            acc.x += a.x;
            acc.y += a.y;
        }
    }
    acc.x += __shfl_xor_sync(0xffffffff, acc.x, 16);
    acc.y += __shfl_xor_sync(0xffffffff, acc.y, 16);
    if (w == 0) {
        ((float2*)(g_agg + (size_t)n * 32))[sub] = acc;
    }
}

// pre-scale: computes BN scale/shift from stats slot, then
// g_xh <- half(relu(bn(g_x)) * norm_src[row])
__global__ void k_prescale(const float* __restrict__ g, const float* __restrict__ bt,
                           int slot) {
    __shared__ float scs[HID], shs[HID];
    int tid = threadIdx.x;
    if (tid < HID) {
        float inv_n = 1.f / (float)NN;
        float mu = g_sum[slot * HID + tid] * inv_n;
        float var = g_sumsq[slot * HID + tid] * inv_n - mu * mu;
        float sc = g[tid] * rsqrtf(var + BN_EPS);
        scs[tid] = sc;
        shs[tid] = bt[tid] - mu * sc;
    }
    __syncthreads();
    int i = blockIdx.x * blockDim.x + threadIdx.x;
    if (i >= NN * (HID / 4)) return;
    int lane = i & 31;
    int row = i >> 5;
    float4 sc = *(const float4*)(scs + lane * 4);
    float4 sh = *(const float4*)(shs + lane * 4);
    float ns = g_norm_src[row];
    float4 v = ((const float4*)g_x)[i];
    float2 lo = make_float2(fmaxf(fmaf(v.x, sc.x, sh.x), 0.f) * ns,
                            fmaxf(fmaf(v.y, sc.y, sh.y), 0.f) * ns);
    float2 hi = make_float2(fmaxf(fmaf(v.z, sc.z, sh.z), 0.f) * ns,
                            fmaxf(fmaf(v.w, sc.w, sh.w), 0.f) * ns);
    __half2 h0 = __float22half2_rn(lo);
    __half2 h1 = __float22half2_rn(hi);
    uint2 packed;
    packed.x = *(unsigned int*)&h0;
    packed.y = *(unsigned int*)&h1;
    ((uint2*)g_xh)[i] = packed;
}

// pure-sum gather, fp16 rows, fp32 accumulation, MLP=16, int4 index loads
__global__ void k_gather128() {
    int gid = blockIdx.x * blockDim.x + threadIdx.x;
    int n = gid >> 5;
    int lane = gid & 31;
    if (n >= NN) return;
    const int* cs = g_csr_src + g_rowptr[n];
    int cnt = g_deg_in_i[n];
    float4 acc = make_float4(0.f, 0.f, 0.f, 0.f);
    const uint2* xh = (const uint2*)g_xh;
    float2 a, bb;
#define ACC(P) \
        a = __half22float2(*(__half2*)&P.x); bb = __half22float2(*(__half2*)&P.y); \
        acc.x += a.x; acc.y += a.y; acc.z += bb.x; acc.w += bb.y;
    int i = 0;
    for (; i + 16 <= cnt; i += 16) {
        int4 ia = *(const int4*)(cs + i);
        int4 ib = *(const int4*)(cs + i + 4);
        int4 ic = *(const int4*)(cs + i + 8);
        int4 id = *(const int4*)(cs + i + 12);
        uint2 p0 = __ldg(xh + (size_t)ia.x * 32 + lane);
        uint2 p1 = __ldg(xh + (size_t)ia.y * 32 + lane);
        uint2 p2 = __ldg(xh + (size_t)ia.z * 32 + lane);
        uint2 p3 = __ldg(xh + (size_t)ia.w * 32 + lane);
        uint2 p4 = __ldg(xh + (size_t)ib.x * 32 + lane);
        uint2 p5 = __ldg(xh + (size_t)ib.y * 32 + lane);
        uint2 p6 = __ldg(xh + (size_t)ib.z * 32 + lane);
        uint2 p7 = __ldg(xh + (size_t)ib.w * 32 + lane);
        uint2 p8 = __ldg(xh + (size_t)ic.x * 32 + lane);
        uint2 p9 = __ldg(xh + (size_t)ic.y * 32 + lane);
        uint2 pa = __ldg(xh + (size_t)ic.z * 32 + lane);
        uint2 pb = __ldg(xh + (size_t)ic.w * 32 + lane);
        uint2 pc = __ldg(xh + (size_t)id.x * 32 + lane);
        uint2 pd = __ldg(xh + (size_t)id.y * 32 + lane);
        uint2 pe = __ldg(xh + (size_t)id.z * 32 + lane);
        uint2 pf = __ldg(xh + (size_t)id.w * 32 + lane);
        ACC(p0) ACC(p1) ACC(p2) ACC(p3) ACC(p4) ACC(p5) ACC(p6) ACC(p7)
        ACC(p8) ACC(p9) ACC(pa) ACC(pb) ACC(pc) ACC(pd) ACC(pe) ACC(pf)
    }
    for (; i + 4 <= cnt; i += 4) {
        int4 ia = *(const int4*)(cs + i);
        uint2 p0 = __ldg(xh + (size_t)ia.x * 32 + lane);
        uint2 p1 = __ldg(xh + (size_t)ia.y * 32 + lane);
        uint2 p2 = __ldg(xh + (size_t)ia.z * 32 + lane);
        uint2 p3 = __ldg(xh + (size_t)ia.w * 32 + lane);
        ACC(p0) ACC(p1) ACC(p2) ACC(p3)
    }
    for (; i < cnt; i++) {
        int s0 = cs[i];
        uint2 p0 = __ldg(xh + (size_t)s0 * 32 + lane);
        ACC(p0)
    }
#undef ACC
    ((float4*)(g_agg + (size_t)n * HID))[lane] = acc;
}

// ---- layer-0 GEMM: 3xTF32, A [NN,32] (zero-padded K), W [26->32,128] ----
#define L0_LDW 132
#define L0_WHI 0
#define L0_WLO (32 * L0_LDW)
#define L0_XHI (2 * 32 * L0_LDW)
#define L0_XLO (2 * 32 * L0_LDW + 64 * L0_LDW)
#define L0_SMEM ((2 * 32 * L0_LDW + 2 * 64 * L0_LDW) * 4)
#define L0_GRID 148
__global__ void __launch_bounds__(256, 1) k_gemm_l0_tf32(const float* __restrict__ W,
                                                         const float* __restrict__ b) {
    extern __shared__ float sm[];
    float* Whi = sm + L0_WHI;
    float* Wlo = sm + L0_WLO;
    float* xhi = sm + L0_XHI;
    float* xlo = sm + L0_XLO;
    int tid = threadIdx.x, lane = tid & 31, warp = tid >> 5;
    int g = lane >> 2, tg = lane & 3;

    for (int i = tid; i < 32 * 32; i += 256) {
        int row = i >> 5, t4 = i & 31;
        float4 v = (row < INC) ? ((const float4*)W)[row * 32 + t4]
                               : make_float4(0.f, 0.f, 0.f, 0.f);
        uint4 hi, lo;
        tf32_split(v.x, hi.x, lo.x);
        tf32_split(v.y, hi.y, lo.y);
        tf32_split(v.z, hi.z, lo.z);
        tf32_split(v.w, hi.w, lo.w);
        *(uint4*)(Whi + row * L0_LDW + t4 * 4) = hi;
        *(uint4*)(Wlo + row * L0_LDW + t4 * 4) = lo;
    }

    int wrow = (warp & 3) * 16;
    int wcol = (warp >> 2) * 64;
    float bcx[8], bcy[8];
#pragma unroll
    for (int nt = 0; nt < 8; nt++) {
        int c = wcol + nt * 8 + 2 * tg;
        bcx[nt] = __ldg(&b[c]);
        bcy[nt] = __ldg(&b[c + 1]);
    }
    float scol[16], qcol[16];
#pragma unroll
    for (int t = 0; t < 16; t++) { scol[t] = 0.f; qcol[t] = 0.f; }

    for (int rb = blockIdx.x * 64; rb < NN; rb += L0_GRID * 64) {
        __syncthreads();
        for (int i = tid; i < 64 * 8; i += 256) {
            int row = i >> 3, t4 = i & 7;
            int gr = rb + row;
            float4 v = (gr < NN) ? ((const float4*)g_agg)[(size_t)gr * 8 + t4]
                                 : make_float4(0.f, 0.f, 0.f, 0.f);
            uint4 hi, lo;
            tf32_split(v.x, hi.x, lo.x);
            tf32_split(v.y, hi.y, lo.y);
            tf32_split(v.z, hi.z, lo.z);
            tf32_split(v.w, hi.w, lo.w);
            *(uint4*)(xhi + row * L0_LDW + t4 * 4) = hi;
            *(uint4*)(xlo + row * L0_LDW + t4 * 4) = lo;
        }
        __syncthreads();

        float d[8][4];
#pragma unroll
        for (int nt = 0; nt < 8; nt++) { d[nt][0]=0.f; d[nt][1]=0.f; d[nt][2]=0.f; d[nt][3]=0.f; }

#pragma unroll
        for (int ks = 0; ks < 4; ks++) {
            int k0 = ks * 8;
            unsigned int ah0 = __float_as_uint(xhi[(wrow + g) * L0_LDW + k0 + tg]);
            unsigned int ah1 = __float_as_uint(xhi[(wrow + g + 8) * L0_LDW + k0 + tg]);
            unsigned int ah2 = __float_as_uint(xhi[(wrow + g) * L0_LDW + k0 + tg + 4]);
            unsigned int ah3 = __float_as_uint(xhi[(wrow + g + 8) * L0_LDW + k0 + tg + 4]);
            unsigned int al0 = __float_as_uint(xlo[(wrow + g) * L0_LDW + k0 + tg]);
            unsigned int al1 = __float_as_uint(xlo[(wrow + g + 8) * L0_LDW + k0 + tg]);
            unsigned int al2 = __float_as_uint(xlo[(wrow + g) * L0_LDW + k0 + tg + 4]);
            unsigned int al3 = __float_as_uint(xlo[(wrow + g + 8) * L0_LDW + k0 + tg + 4]);
#pragma unroll
            for (int nt = 0; nt < 8; nt++) {
                int bcol = wcol + nt * 8 + g;
                unsigned int bh0 = __float_as_uint(Whi[(k0 + tg) * L0_LDW + bcol]);
                unsigned int bh1 = __float_as_uint(Whi[(k0 + tg + 4) * L0_LDW + bcol]);
                unsigned int bl0 = __float_as_uint(Wlo[(k0 + tg) * L0_LDW + bcol]);
                unsigned int bl1 = __float_as_uint(Wlo[(k0 + tg + 4) * L0_LDW + bcol]);
#define MMA(A0,A1,A2,A3,B0,B1) \
                asm volatile( \
                    "mma.sync.aligned.m16n8k8.row.col.f32.tf32.tf32.f32 " \
                    "{%0,%1,%2,%3}, {%4,%5,%6,%7}, {%8,%9}, {%0,%1,%2,%3};" \
                    : "+f"(d[nt][0]), "+f"(d[nt][1]), "+f"(d[nt][2]), "+f"(d[nt][3]) \
                    : "r"(A0), "r"(A1), "r"(A2), "r"(A3), "r"(B0), "r"(B1));
                MMA(ah0, ah1, ah2, ah3, bh0, bh1)
                MMA(ah0, ah1, ah2, ah3, bl0, bl1)
                MMA(al0, al1, al2, al3, bh0, bh1)
#undef MMA
            }
        }

        int r0 = rb + wrow + g;
        int r1 = r0 + 8;
        bool v0 = r0 < NN, v1 = r1 < NN;
        float nd0 = v0 ? g_norm_dst[r0] : 0.f;
        float nd1 = v1 ? g_norm_dst[r1] : 0.f;
#pragma unroll
        for (int nt = 0; nt < 8; nt++) {
            int c = wcol + nt * 8 + 2 * tg;
            if (v0) {
                float yx = d[nt][0] * nd0 + bcx[nt];
                float yy = d[nt][1] * nd0 + bcy[nt];
                *(float2*)(g_x + (size_t)r0 * HID + c) = make_float2(yx, yy);
                scol[nt * 2] += yx;     qcol[nt * 2]     = fmaf(yx, yx, qcol[nt * 2]);
                scol[nt * 2 + 1] += yy; qcol[nt * 2 + 1] = fmaf(yy, yy, qcol[nt * 2 + 1]);
            }
            if (v1) {
                float yx = d[nt][2] * nd1 + bcx[nt];
                float yy = d[nt][3] * nd1 + bcy[nt];
                *(float2*)(g_x + (size_t)r1 * HID + c) = make_float2(yx, yy);
                scol[nt * 2] += yx;     qcol[nt * 2]     = fmaf(yx, yx, qcol[nt * 2]);
                scol[nt * 2 + 1] += yy; qcol[nt * 2 + 1] = fmaf(yy, yy, qcol[nt * 2 + 1]);
            }
        }
    }

#pragma unroll
    for (int t = 0; t < 16; t++) {
        scol[t] += __shfl_xor_sync(0xffffffff, scol[t], 4);
        scol[t] += __shfl_xor_sync(0xffffffff, scol[t], 8);
        scol[t] += __shfl_xor_sync(0xffffffff, scol[t], 16);
        qcol[t] += __shfl_xor_sync(0xffffffff, qcol[t], 4);
        qcol[t] += __shfl_xor_sync(0xffffffff, qcol[t], 8);
        qcol[t] += __shfl_xor_sync(0xffffffff, qcol[t], 16);
    }
    if (g == 0) {
#pragma unroll
        for (int nt = 0; nt < 8; nt++) {
            int c = wcol + nt * 8 + 2 * tg;
            atomicAdd(&g_sum[c],     scol[nt * 2]);
            atomicAdd(&g_sum[c + 1], scol[nt * 2 + 1]);
            atomicAdd(&g_sumsq[c],     qcol[nt * 2]);
            atomicAdd(&g_sumsq[c + 1], qcol[nt * 2 + 1]);
        }
    }
}

// ---- hidden GEMM: 3xTF32 error-compensated tensor cores, persistent ----
#define GT_GRID 148
#define GT_LDW 132
#define GT_WHI 0
#define GT_WLO (128 * GT_LDW)
#define GT_XHI (2 * 128 * GT_LDW)
#define GT_XLO (2 * 128 * GT_LDW + 64 * GT_LDW)
#define GT_SMEM ((2 * 128 * GT_LDW + 2 * 64 * GT_LDW) * 4)
__global__ void __launch_bounds__(256, 1) k_gemm_tf32(const float* __restrict__ W,
                                                      const float* __restrict__ b,
                                                      int slot) {
    extern __shared__ float sm[];
    float* Whi = sm + GT_WHI;
    float* Wlo = sm + GT_WLO;
    float* xhi = sm + GT_XHI;
    float* xlo = sm + GT_XLO;
    int tid = threadIdx.x, lane = tid & 31, warp = tid >> 5;
    int g = lane >> 2, tg = lane & 3;

    for (int i = tid; i < 128 * 32; i += 256) {
        int row = i >> 5, t4 = i & 31;
        float4 v = ((const float4*)W)[i];
        uint4 hi, lo;
        tf32_split(v.x, hi.x, lo.x);
        tf32_split(v.y, hi.y, lo.y);
        tf32_split(v.z, hi.z, lo.z);
        tf32_split(v.w, hi.w, lo.w);
        *(uint4*)(Whi + row * GT_LDW + t4 * 4) = hi;
        *(uint4*)(Wlo + row * GT_LDW + t4 * 4) = lo;
    }

    int wrow = (warp & 3) * 16;
    int wcol = (warp >> 2) * 64;
    float bcx[8], bcy[8];
#pragma unroll
    for (int nt = 0; nt < 8; nt++) {
        int c = wcol + nt * 8 + 2 * tg;
        bcx[nt] = __ldg(&b[c]);
        bcy[nt] = __ldg(&b[c + 1]);
    }
    float scol[16], qcol[16];
#pragma unroll
    for (int t = 0; t < 16; t++) { scol[t] = 0.f; qcol[t] = 0.f; }

    for (int rb = blockIdx.x * 64; rb < NN; rb += GT_GRID * 64) {
        __syncthreads();
        for (int i = tid; i < 64 * 32; i += 256) {
            int row = i >> 5, t4 = i & 31;
            int gr = rb + row;
            float4 v = (gr < NN) ? ((const float4*)g_agg)[(size_t)gr * 32 + t4]
                                 : make_float4(0.f, 0.f, 0.f, 0.f);
            uint4 hi, lo;
            tf32_split(v.x, hi.x, lo.x);
            tf32_split(v.y, hi.y, lo.y);
            tf32_split(v.z, hi.z, lo.z);
            tf32_split(v.w, hi.w, lo.w);
            *(uint4*)(xhi + row * GT_LDW + t4 * 4) = hi;
            *(uint4*)(xlo + row * GT_LDW + t4 * 4) = lo;
        }
        __syncthreads();

        float d[8][4];
#pragma unroll
        for (int nt = 0; nt < 8; nt++) { d[nt][0]=0.f; d[nt][1]=0.f; d[nt][2]=0.f; d[nt][3]=0.f; }

#pragma unroll
        for (int ks = 0; ks < 16; ks++) {
            int k0 = ks * 8;
            unsigned int ah0 = __float_as_uint(xhi[(wrow + g) * GT_LDW + k0 + tg]);
            unsigned int ah1 = __float_as_uint(xhi[(wrow + g + 8) * GT_LDW + k0 + tg]);
            unsigned int ah2 = __float_as_uint(xhi[(wrow + g) * GT_LDW + k0 + tg + 4]);
            unsigned int ah3 = __float_as_uint(xhi[(wrow + g + 8) * GT_LDW + k0 + tg + 4]);
            unsigned int al0 = __float_as_uint(xlo[(wrow + g) * GT_LDW + k0 + tg]);
            unsigned int al1 = __float_as_uint(xlo[(wrow + g + 8) * GT_LDW + k0 + tg]);
            unsigned int al2 = __float_as_uint(xlo[(wrow + g) * GT_LDW + k0 + tg + 4]);
            unsigned int al3 = __float_as_uint(xlo[(wrow + g + 8) * GT_LDW + k0 + tg + 4]);
#pragma unroll
            for (int nt = 0; nt < 8; nt++) {
                int bcol = wcol + nt * 8 + g;
                unsigned int bh0 = __float_as_uint(Whi[(k0 + tg) * GT_LDW + bcol]);
                unsigned int bh1 = __float_as_uint(Whi[(k0 + tg + 4) * GT_LDW + bcol]);
                unsigned int bl0 = __float_as_uint(Wlo[(k0 + tg) * GT_LDW + bcol]);
                unsigned int bl1 = __float_as_uint(Wlo[(k0 + tg + 4) * GT_LDW + bcol]);
#define MMA(A0,A1,A2,A3,B0,B1) \
                asm volatile( \
                    "mma.sync.aligned.m16n8k8.row.col.f32.tf32.tf32.f32 " \
                    "{%0,%1,%2,%3}, {%4,%5,%6,%7}, {%8,%9}, {%0,%1,%2,%3};" \
                    : "+f"(d[nt][0]), "+f"(d[nt][1]), "+f"(d[nt][2]), "+f"(d[nt][3]) \
                    : "r"(A0), "r"(A1), "r"(A2), "r"(A3), "r"(B0), "r"(B1));
                MMA(ah0, ah1, ah2, ah3, bh0, bh1)
                MMA(ah0, ah1, ah2, ah3, bl0, bl1)
                MMA(al0, al1, al2, al3, bh0, bh1)
#undef MMA
            }
        }

        int r0 = rb + wrow + g;
        int r1 = r0 + 8;
        bool v0 = r0 < NN, v1 = r1 < NN;
        float nd0 = v0 ? g_norm_dst[r0] : 0.f;
        float nd1 = v1 ? g_norm_dst[r1] : 0.f;
#pragma unroll
        for (int nt = 0; nt < 8; nt++) {
            int c = wcol + nt * 8 + 2 * tg;
            if (v0) {
                float yx = d[nt][0] * nd0 + bcx[nt];
                float yy = d[nt][1] * nd0 + bcy[nt];
                *(float2*)(g_x + (size_t)r0 * HID + c) = make_float2(yx, yy);
                scol[nt * 2] += yx;     qcol[nt * 2]     = fmaf(yx, yx, qcol[nt * 2]);
                scol[nt * 2 + 1] += yy; qcol[nt * 2 + 1] = fmaf(yy, yy, qcol[nt * 2 + 1]);
            }
            if (v1) {
                float yx = d[nt][2] * nd1 + bcx[nt];
                float yy = d[nt][3] * nd1 + bcy[nt];
                *(float2*)(g_x + (size_t)r1 * HID + c) = make_float2(yx, yy);
                scol[nt * 2] += yx;     qcol[nt * 2]     = fmaf(yx, yx, qcol[nt * 2]);
                scol[nt * 2 + 1] += yy; qcol[nt * 2 + 1] = fmaf(yy, yy, qcol[nt * 2 + 1]);
            }
        }
    }

#pragma unroll
    for (int t = 0; t < 16; t++) {
        scol[t] += __shfl_xor_sync(0xffffffff, scol[t], 4);
        scol[t] += __shfl_xor_sync(0xffffffff, scol[t], 8);
        scol[t] += __shfl_xor_sync(0xffffffff, scol[t], 16);
        qcol[t] += __shfl_xor_sync(0xffffffff, qcol[t], 4);
        qcol[t] += __shfl_xor_sync(0xffffffff, qcol[t], 8);
        qcol[t] += __shfl_xor_sync(0xffffffff, qcol[t], 16);
    }
    if (g == 0) {
        float* gsum = g_sum + slot * HID;
        float* gsq  = g_sumsq + slot * HID;
#pragma unroll
        for (int nt = 0; nt < 8; nt++) {
            int c = wcol + nt * 8 + 2 * tg;
            atomicAdd(&gsum[c],     scol[nt * 2]);
            atomicAdd(&gsum[c + 1], scol[nt * 2 + 1]);
            atomicAdd(&gsq[c],      qcol[nt * 2]);
            atomicAdd(&gsq[c + 1],  qcol[nt * 2 + 1]);
        }
    }
}

// ---- final FC: 3xTF32; BN2+ReLU (computed from stats slot 2) fused in staging ----
#define FC_GRID 148
#define FC_LDWW 68
#define FC_LDX 132
#define FC_WHI 0
#define FC_WLO (128 * FC_LDWW)
#define FC_XHI (2 * 128 * FC_LDWW)
#define FC_XLO (2 * 128 * FC_LDWW + 64 * FC_LDX)
#define FC_SC  (2 * 128 * FC_LDWW + 2 * 64 * FC_LDX)
#define FC_SMEM ((2 * 128 * FC_LDWW + 2 * 64 * FC_LDX + 2 * HID) * 4)
__global__ void __launch_bounds__(256, 1) k_fc_tf32(const float* __restrict__ W,
                                                    const float* __restrict__ b,
                                                    const float* __restrict__ gam,
                                                    const float* __restrict__ bet,
                                                    float* __restrict__ out) {
    extern __shared__ float sm[];
    float* Whi = sm + FC_WHI;
    float* Wlo = sm + FC_WLO;
    float* xhi = sm + FC_XHI;
    float* xlo = sm + FC_XLO;
    float* scs = sm + FC_SC;
    float* shs = scs + HID;
    int tid = threadIdx.x, lane = tid & 31, warp = tid >> 5;
    int g = lane >> 2, tg = lane & 3;

    if (tid < HID) {
        float inv_n = 1.f / (float)NN;
        float mu = g_sum[2 * HID + tid] * inv_n;
        float var = g_sumsq[2 * HID + tid] * inv_n - mu * mu;
        float sc = gam[tid] * rsqrtf(var + BN_EPS);
        scs[tid] = sc;
        shs[tid] = bet[tid] - mu * sc;
    }
    for (int i = tid; i < 128 * 16; i += 256) {
        int row = i >> 4, t4 = i & 15;
        float4 v = ((const float4*)W)[i];
        uint4 hi, lo;
        tf32_split(v.x, hi.x, lo.x);
        tf32_split(v.y, hi.y, lo.y);
        tf32_split(v.z, hi.z, lo.z);
        tf32_split(v.w, hi.w, lo.w);
        *(uint4*)(Whi + row * FC_LDWW + t4 * 4) = hi;
        *(uint4*)(Wlo + row * FC_LDWW + t4 * 4) = lo;
    }

    int wrow = (warp & 3) * 16;
    int wcol = (warp >> 2) * 32;
    float bcx[4], bcy[4];
#pragma unroll
    for (int nt = 0; nt < 4; nt++) {
        int c = wcol + nt * 8 + 2 * tg;
        bcx[nt] = __ldg(&b[c]);
        bcy[nt] = __ldg(&b[c + 1]);
    }
    __syncthreads();

    for (int rb = blockIdx.x * 64; rb < NN; rb += FC_GRID * 64) {
        __syncthreads();
        for (int i = tid; i < 64 * 32; i += 256) {
            int row = i >> 5, t4 = i & 31;
            int gr = rb + row;
            float4 v = (gr < NN) ? ((const float4*)g_x)[(size_t)gr * 32 + t4]
                                 : make_float4(0.f, 0.f, 0.f, 0.f);
            int k = t4 * 4;
            v.x = fmaxf(fmaf(v.x, scs[k + 0], shs[k + 0]), 0.f);
            v.y = fmaxf(fmaf(v.y, scs[k + 1], shs[k + 1]), 0.f);
            v.z = fmaxf(fmaf(v.z, scs[k + 2], shs[k + 2]), 0.f);
            v.w = fmaxf(fmaf(v.w, scs[k + 3], shs[k + 3]), 0.f);
            uint4 hi, lo;
            tf32_split(v.x, hi.x, lo.x);
            tf32_split(v.y, hi.y, lo.y);
            tf32_split(v.z, hi.z, lo.z);
            tf32_split(v.w, hi.w, lo.w);
            *(uint4*)(xhi + row * FC_LDX + t4 * 4) = hi;
            *(uint4*)(xlo + row * FC_LDX + t4 * 4) = lo;
        }
        __syncthreads();

        float d[4][4];
#pragma unroll
        for (int nt = 0; nt < 4; nt++) { d[nt][0]=0.f; d[nt][1]=0.f; d[nt][2]=0.f; d[nt][3]=0.f; }

#pragma unroll
        for (int ks = 0; ks < 16; ks++) {
            int k0 = ks * 8;
            unsigned int ah0 = __float_as_uint(xhi[(wrow + g) * FC_LDX + k0 + tg]);
            unsigned int ah1 = __float_as_uint(xhi[(wrow + g + 8) * FC_LDX + k0 + tg]);
            unsigned int ah2 = __float_as_uint(xhi[(wrow + g) * FC_LDX + k0 + tg + 4]);
            unsigned int ah3 = __float_as_uint(xhi[(wrow + g + 8) * FC_LDX + k0 + tg + 4]);
            unsigned int al0 = __float_as_uint(xlo[(wrow + g) * FC_LDX + k0 + tg]);
            unsigned int al1 = __float_as_uint(xlo[(wrow + g + 8) * FC_LDX + k0 + tg]);
            unsigned int al2 = __float_as_uint(xlo[(wrow + g) * FC_LDX + k0 + tg + 4]);
            unsigned int al3 = __float_as_uint(xlo[(wrow + g + 8) * FC_LDX + k0 + tg + 4]);
#pragma unroll
            for (int nt = 0; nt < 4; nt++) {
                int bcol = wcol + nt * 8 + g;
                unsigned int bh0 = __float_as_uint(Whi[(k0 + tg) * FC_LDWW + bcol]);
                unsigned int bh1 = __float_as_uint(Whi[(k0 + tg + 4) * FC_LDWW + bcol]);
                unsigned int bl0 = __float_as_uint(Wlo[(k0 + tg) * FC_LDWW + bcol]);
                unsigned int bl1 = __float_as_uint(Wlo[(k0 + tg + 4) * FC_LDWW + bcol]);
#define MMA(A0,A1,A2,A3,B0,B1) \
                asm volatile( \
                    "mma.sync.aligned.m16n8k8.row.col.f32.tf32.tf32.f32 " \
                    "{%0,%1,%2,%3}, {%4,%5,%6,%7}, {%8,%9}, {%0,%1,%2,%3};" \
                    : "+f"(d[nt][0]), "+f"(d[nt][1]), "+f"(d[nt][2]), "+f"(d[nt][3]) \
                    : "r"(A0), "r"(A1), "r"(A2), "r"(A3), "r"(B0), "r"(B1));
                MMA(ah0, ah1, ah2, ah3, bh0, bh1)
                MMA(ah0, ah1, ah2, ah3, bl0, bl1)
                MMA(al0, al1, al2, al3, bh0, bh1)
#undef MMA
            }
        }

        int r0 = rb + wrow + g;
        int r1 = r0 + 8;
#pragma unroll
        for (int nt = 0; nt < 4; nt++) {
            int c = wcol + nt * 8 + 2 * tg;
            if (r0 < NN)
                *(float2*)(out + (size_t)r0 * OUTC + c) =
                    make_float2(d[nt][0] + bcx[nt], d[nt][1] + bcy[nt]);
            if (r1 < NN)
                *(float2*)(out + (size_t)r1 * OUTC + c) =
                    make_float2(d[nt][2] + bcx[nt], d[nt][3] + bcy[nt]);
        }
    }
}

// ---------------- launch ----------------
extern "C" void kernel_launch(void* const* d_in, const int* in_sizes, int n_in,
                              void* d_out, int out_size) {
    const float* h   = (const float*)d_in[0];
    const int*   src = (const int*)d_in[1];
    const int*   dst = (const int*)d_in[2];
    const float* w0  = (const float*)d_in[3];
    const float* b0  = (const float*)d_in[4];
    const float* w1  = (const float*)d_in[5];
    const float* b1  = (const float*)d_in[6];
    const float* w2  = (const float*)d_in[7];
    const float* b2  = (const float*)d_in[8];
    const float* g0  = (const float*)d_in[9];
    const float* bt0 = (const float*)d_in[10];
    const float* g1  = (const float*)d_in[11];
    const float* bt1 = (const float*)d_in[12];
    const float* g2  = (const float*)d_in[13];
    const float* bt2 = (const float*)d_in[14];
    const float* wfc = (const float*)d_in[15];
    const float* bfc = (const float*)d_in[16];
    float* out = (float*)d_out;

    cudaFuncSetAttribute(k_gemm_tf32, cudaFuncAttributeMaxDynamicSharedMemorySize, GT_SMEM);
    cudaFuncSetAttribute(k_gemm_l0_tf32, cudaFuncAttributeMaxDynamicSharedMemorySize, L0_SMEM);
    cudaFuncSetAttribute(k_fc_tf32, cudaFuncAttributeMaxDynamicSharedMemorySize, FC_SMEM);

    // graph prep: degrees, norms, node weights, fp16 layer-0 messages, CSR
    k_zero_deg<<<(NN + 255) / 256, 256>>>();   // also zeros all BN stat slots
    k_degrees<<<(NE + 255) / 256, 256>>>(src, dst);
    k_nodeprep<<<(NN + 255) / 256, 256>>>(h, out);
    k_alloc<<<(NN + 255) / 256, 256>>>();      // 4-aligned CSR segments
    k_fill<<<(NE + 255) / 256, 256>>>(src, dst);

    // ---- layer 0 (26 -> 128), 3xTF32, stats -> slot 0 ----
    k_gather26<<<(NN * 32 + 255) / 256, 256>>>();
    k_gemm_l0_tf32<<<L0_GRID, 256, L0_SMEM>>>(w0, b0);

    // ---- layers 1, 2 (128 -> 128), 3xTF32, stats -> slots 1, 2 ----
    const float* Ws[2]  = {w1, w2};
    const float* bs[2]  = {b1, b2};
    const float* gs[2]  = {g0, g1};
    const float* bts[2] = {bt0, bt1};
    for (int l = 0; l < 2; l++) {
        k_prescale<<<(NN * (HID / 4) + 255) / 256, 256>>>(gs[l], bts[l], l);
        k_gather128<<<(NN * 32 + 255) / 256, 256>>>();
        k_gemm_tf32<<<GT_GRID, 256, GT_SMEM>>>(Ws[l], bs[l], l + 1);
    }

    // ---- final FC (128 -> 64), 3xTF32, BN2+ReLU from slot 2 fused in staging ----
    k_fc_tf32<<<FC_GRID, 256, FC_SMEM>>>(wfc, bfc, g2, bt2, out);
}